// round 1
// baseline (speedup 1.0000x reference)
#include <cuda_runtime.h>
#include <math.h>

#define N_NODES 50000
#define N_EDGES 800000
#define E_TOT   850000   // edges + self loops
#define U       64
#define NG      512
#define F_IN    9

// ---------------- scratch (device globals; no allocations) ----------------
__device__ float    g_h[N_NODES * U];     // linear-layer output (gather source)
__device__ float    g_x[N_NODES * U];     // current activation
__device__ float    g_out[N_NODES * U];   // scatter accumulator
__device__ float    g_as[N_NODES];
__device__ float    g_ad[N_NODES];
__device__ float    g_e[E_TOT];           // e -> ex -> coef (in place)
__device__ float    g_ncoef[E_TOT];       // GCN symmetric norm per edge
__device__ unsigned g_m[N_NODES];         // ordered-encoded segment max
__device__ float    g_denom[N_NODES];
__device__ float    g_deg[N_NODES];
__device__ float    g_dinv[N_NODES];
__device__ float    g_psum[2 * NG];
__device__ float    g_pcnt[2 * NG];

// ---------------- helpers ----------------
__device__ __forceinline__ unsigned f2ord(float f) {
    unsigned u = __float_as_uint(f);
    return (u & 0x80000000u) ? ~u : (u | 0x80000000u);
}
__device__ __forceinline__ float ord2f(unsigned k) {
    unsigned u = (k & 0x80000000u) ? (k ^ 0x80000000u) : ~k;
    return __uint_as_float(u);
}
__device__ __forceinline__ void red_add_v4(float* p, float4 v) {
    unsigned long long gp;
    asm("cvta.to.global.u64 %0, %1;" : "=l"(gp) : "l"(p));
    asm volatile("red.global.add.v4.f32 [%0], {%1,%2,%3,%4};"
                 :: "l"(gp), "f"(v.x), "f"(v.y), "f"(v.z), "f"(v.w) : "memory");
}
__device__ __forceinline__ void edge_src_dst(int e, const int* __restrict__ ei,
                                             int& src, int& dst) {
    if (e < N_EDGES) { src = ei[e]; dst = ei[N_EDGES + e]; }
    else             { src = e - N_EDGES; dst = src; }
}

// ---------------- init ----------------
__global__ void k_init_node() {
    int i = blockIdx.x * blockDim.x + threadIdx.x;
    if (i < N_NODES) { g_m[i] = 0u; g_denom[i] = 0.f; g_deg[i] = 0.f; }
}
__global__ void k_zero_out() {
    int i = blockIdx.x * blockDim.x + threadIdx.x;
    if (i < N_NODES * U) g_out[i] = 0.f;
}
__global__ void k_init_pool() {
    int i = blockIdx.x * blockDim.x + threadIdx.x;
    if (i < 2 * NG) { g_psum[i] = 0.f; g_pcnt[i] = 0.f; }
}

// ---------------- GAT linear + attention logits ----------------
__global__ void k_gat_lin(const float* __restrict__ x, const float* __restrict__ Wg,
                          const float* __restrict__ a_src, const float* __restrict__ a_dst) {
    __shared__ float Ws[F_IN * U];
    __shared__ float as_s[U], ad_s[U];
    int tid = threadIdx.x;
    for (int i = tid; i < F_IN * U; i += blockDim.x) Ws[i] = Wg[i];
    if (tid < U) { as_s[tid] = a_src[tid]; ad_s[tid] = a_dst[tid]; }
    __syncthreads();
    int lane = tid & 31, w = tid >> 5;
    int node = blockIdx.x * (blockDim.x >> 5) + w;
    if (node >= N_NODES) return;
    float acc0 = 0.f, acc1 = 0.f;
#pragma unroll
    for (int j = 0; j < F_IN; j++) {
        float v = __ldg(&x[node * F_IN + j]);   // broadcast across warp
        acc0 += v * Ws[j * U + lane];
        acc1 += v * Ws[j * U + lane + 32];
    }
    g_h[node * U + lane]      = acc0;
    g_h[node * U + lane + 32] = acc1;
    float s = acc0 * as_s[lane] + acc1 * as_s[lane + 32];
    float d = acc0 * ad_s[lane] + acc1 * ad_s[lane + 32];
#pragma unroll
    for (int o = 16; o > 0; o >>= 1) {
        s += __shfl_xor_sync(0xffffffffu, s, o);
        d += __shfl_xor_sync(0xffffffffu, d, o);
    }
    if (lane == 0) { g_as[node] = s; g_ad[node] = d; }
}

// ---------------- GAT edge passes ----------------
__global__ void k_gat_e(const int* __restrict__ ei) {   // e = lrelu, seg-max, degree
    int e = blockIdx.x * blockDim.x + threadIdx.x;
    if (e >= E_TOT) return;
    int src, dst; edge_src_dst(e, ei, src, dst);
    float v = g_as[src] + g_ad[dst];
    v = v > 0.f ? v : 0.2f * v;
    g_e[e] = v;
    atomicMax(&g_m[dst], f2ord(v));
    atomicAdd(&g_deg[dst], 1.0f);
}
__global__ void k_gat_ex(const int* __restrict__ ei) {  // ex = exp(e-m), seg-sum
    int e = blockIdx.x * blockDim.x + threadIdx.x;
    if (e >= E_TOT) return;
    int dst = (e < N_EDGES) ? ei[N_EDGES + e] : (e - N_EDGES);
    float m  = ord2f(g_m[dst]);
    float ex = __expf(g_e[e] - m);
    g_e[e] = ex;
    atomicAdd(&g_denom[dst], ex);
}
__global__ void k_gat_coef(const int* __restrict__ ei) { // coef = ex/denom[dst]
    int e = blockIdx.x * blockDim.x + threadIdx.x;
    if (e >= E_TOT) return;
    int dst = (e < N_EDGES) ? ei[N_EDGES + e] : (e - N_EDGES);
    g_e[e] = g_e[e] / g_denom[dst];
}

// ---------------- feature scatter: out[dst] += h[src] * coef ----------------
__global__ void k_scatter(const int* __restrict__ ei, int use_norm) {
    int idx = blockIdx.x * blockDim.x + threadIdx.x;
    int e = idx >> 4, c = idx & 15;
    if (e >= E_TOT) return;
    int src, dst; edge_src_dst(e, ei, src, dst);
    const float* __restrict__ coef = use_norm ? g_ncoef : g_e;
    float cf = coef[e];
    float4 hv = reinterpret_cast<const float4*>(g_h)[src * 16 + c];
    float4 v = make_float4(hv.x * cf, hv.y * cf, hv.z * cf, hv.w * cf);
    red_add_v4(g_out + (size_t)dst * U + c * 4, v);
}

// ---------------- bias + tanh, and re-zero the accumulator ----------------
__global__ void k_bias_tanh(const float* __restrict__ b) {
    int i = blockIdx.x * blockDim.x + threadIdx.x;
    if (i >= N_NODES * U) return;
    g_x[i] = tanhf(g_out[i] + b[i & 63]);
    g_out[i] = 0.f;
}

// ---------------- GCN normalization ----------------
__global__ void k_dinv() {
    int i = blockIdx.x * blockDim.x + threadIdx.x;
    if (i < N_NODES) g_dinv[i] = rsqrtf(g_deg[i]);  // deg >= 1 (self loop)
}
__global__ void k_norm(const int* __restrict__ ei) {
    int e = blockIdx.x * blockDim.x + threadIdx.x;
    if (e >= E_TOT) return;
    int src, dst; edge_src_dst(e, ei, src, dst);
    g_ncoef[e] = g_dinv[src] * g_dinv[dst];
}

// ---------------- 64x64 GEMM: g_h = g_x @ W ----------------
__global__ void k_gemm64(const float* __restrict__ W) {
    __shared__ float Ws[U * U];
    int tid = threadIdx.x;
    for (int i = tid; i < U * U; i += blockDim.x) Ws[i] = W[i];
    __syncthreads();
    int lane = tid & 31, w = tid >> 5;
    int base = (blockIdx.x * (blockDim.x >> 5) + w) * 4;
    if (base >= N_NODES) return;
    int nv = min(4, N_NODES - base);
    float xlo[4], xhi[4], a0[4] = {0,0,0,0}, a1[4] = {0,0,0,0};
#pragma unroll
    for (int n = 0; n < 4; n++) {
        int node = base + (n < nv ? n : 0);
        xlo[n] = g_x[node * U + lane];
        xhi[n] = g_x[node * U + lane + 32];
    }
#pragma unroll
    for (int k = 0; k < U; k++) {
        float w0 = Ws[k * U + lane], w1 = Ws[k * U + lane + 32];
#pragma unroll
        for (int n = 0; n < 4; n++) {
            float v = (k < 32) ? __shfl_sync(0xffffffffu, xlo[n], k)
                               : __shfl_sync(0xffffffffu, xhi[n], k - 32);
            a0[n] += v * w0;
            a1[n] += v * w1;
        }
    }
    for (int n = 0; n < nv; n++) {
        g_h[(base + n) * U + lane]      = a0[n];
        g_h[(base + n) * U + lane + 32] = a1[n];
    }
}

// ---------------- fused MLP (64->64->32->1) + mean-pool accumulate ----------------
__global__ void k_mlp_pool(const int* __restrict__ batch,
                           const float* __restrict__ W1, const float* __restrict__ b1,
                           const float* __restrict__ W2, const float* __restrict__ b2,
                           const float* __restrict__ W3, const float* __restrict__ b3,
                           int poff) {
    __shared__ float W1s[U * U], W2s[U * 32], b1s[U], b2s[32], W3s[32], b3s;
    int tid = threadIdx.x;
    for (int i = tid; i < U * U; i += blockDim.x)  W1s[i] = W1[i];
    for (int i = tid; i < U * 32; i += blockDim.x) W2s[i] = W2[i];
    if (tid < U)  b1s[tid] = b1[tid];
    if (tid < 32) { b2s[tid] = b2[tid]; W3s[tid] = W3[tid]; }
    if (tid == 0) b3s = b3[0];
    __syncthreads();
    int lane = tid & 31, w = tid >> 5;
    int node = blockIdx.x * (blockDim.x >> 5) + w;
    if (node >= N_NODES) return;
    float xlo = g_x[node * U + lane], xhi = g_x[node * U + lane + 32];
    float a0 = b1s[lane], a1 = b1s[lane + 32];
#pragma unroll
    for (int k = 0; k < U; k++) {
        float v = (k < 32) ? __shfl_sync(0xffffffffu, xlo, k)
                           : __shfl_sync(0xffffffffu, xhi, k - 32);
        a0 += v * W1s[k * U + lane];
        a1 += v * W1s[k * U + lane + 32];
    }
    float y1lo = tanhf(a0), y1hi = tanhf(a1);
    float a2 = b2s[lane];
#pragma unroll
    for (int k = 0; k < U; k++) {
        float v = (k < 32) ? __shfl_sync(0xffffffffu, y1lo, k)
                           : __shfl_sync(0xffffffffu, y1hi, k - 32);
        a2 += v * W2s[k * 32 + lane];
    }
    float y2 = tanhf(a2);
    float c = y2 * W3s[lane];
#pragma unroll
    for (int o = 16; o > 0; o >>= 1) c += __shfl_xor_sync(0xffffffffu, c, o);
    if (lane == 0) {
        float y = c + b3s;
        int g = batch[node];
        atomicAdd(&g_psum[poff + g], y);
        atomicAdd(&g_pcnt[poff + g], 1.0f);
    }
}

// ---------------- final: sigmoid(mean_b - mean_a) ----------------
__global__ void k_final(float* __restrict__ out) {
    int g = blockIdx.x * blockDim.x + threadIdx.x;
    if (g >= NG) return;
    float ua = g_psum[g]      / fmaxf(g_pcnt[g], 1.f);
    float ub = g_psum[NG + g] / fmaxf(g_pcnt[NG + g], 1.f);
    out[g] = 1.f / (1.f + expf(-(ub - ua)));
}

// ---------------- host orchestration ----------------
static void run_branch(const float* x, const int* ei, const int* batch,
                       const float* Wgat, const float* a_src, const float* a_dst, const float* bgat,
                       const float* Wgcn, const float* bgcn,
                       const float* W1, const float* b1, const float* W2, const float* b2,
                       const float* W3, const float* b3, int poff) {
    const int NB_N  = (N_NODES + 255) / 256;
    const int NB_NU = (N_NODES * U + 255) / 256;
    const int NB_E  = (E_TOT + 255) / 256;
    const int NB_S  = (E_TOT * 16 + 255) / 256;
    const int NB_W  = (N_NODES + 7) / 8;      // 1 node per warp, 8 warps/block

    k_init_node<<<NB_N, 256>>>();
    k_zero_out<<<NB_NU, 256>>>();
    k_gat_lin<<<NB_W, 256>>>(x, Wgat, a_src, a_dst);
    k_gat_e<<<NB_E, 256>>>(ei);
    k_gat_ex<<<NB_E, 256>>>(ei);
    k_gat_coef<<<NB_E, 256>>>(ei);
    k_scatter<<<NB_S, 256>>>(ei, 0);
    k_bias_tanh<<<NB_NU, 256>>>(bgat);
    k_dinv<<<NB_N, 256>>>();
    k_norm<<<NB_E, 256>>>(ei);
    for (int l = 0; l < 2; l++) {
        k_gemm64<<<(N_NODES + 31) / 32, 256>>>(Wgcn + l * U * U);
        k_scatter<<<NB_S, 256>>>(ei, 1);
        k_bias_tanh<<<NB_NU, 256>>>(bgcn + l * U);
    }
    k_mlp_pool<<<NB_W, 256>>>(batch, W1, b1, W2, b2, W3, b3, poff);
}

extern "C" void kernel_launch(void* const* d_in, const int* in_sizes, int n_in,
                              void* d_out, int out_size) {
    const float* x_a   = (const float*)d_in[0];
    const float* x_b   = (const float*)d_in[1];
    const int*   ei_a  = (const int*)  d_in[2];
    const int*   ei_b  = (const int*)  d_in[3];
    const int*   ba    = (const int*)  d_in[4];
    const int*   bb    = (const int*)  d_in[5];
    const float* Wgat  = (const float*)d_in[6];
    const float* a_src = (const float*)d_in[7];
    const float* a_dst = (const float*)d_in[8];
    const float* bgat  = (const float*)d_in[9];
    const float* Wgcn  = (const float*)d_in[10];
    const float* bgcn  = (const float*)d_in[11];
    const float* W1    = (const float*)d_in[12];
    const float* b1    = (const float*)d_in[13];
    const float* W2    = (const float*)d_in[14];
    const float* b2    = (const float*)d_in[15];
    const float* W3    = (const float*)d_in[16];
    const float* b3    = (const float*)d_in[17];

    k_init_pool<<<4, 256>>>();
    run_branch(x_a, ei_a, ba, Wgat, a_src, a_dst, bgat, Wgcn, bgcn,
               W1, b1, W2, b2, W3, b3, 0);
    run_branch(x_b, ei_b, bb, Wgat, a_src, a_dst, bgat, Wgcn, bgcn,
               W1, b1, W2, b2, W3, b3, NG);
    k_final<<<2, 256>>>((float*)d_out);
}

// round 2
// speedup vs baseline: 1.3063x; 1.3063x over previous
#include <cuda_runtime.h>
#include <math.h>

#define N_NODES 50000
#define N_EDGES 800000
#define E_TOT   850000   // edges + self loops
#define U       64
#define NG      512
#define F_IN    9
#define SCAN_B  1024
#define SCAN_NB ((N_NODES + SCAN_B - 1) / SCAN_B)   // 49

// ---------------- scratch (device globals; no allocations) ----------------
__device__ float g_h[N_NODES * U];     // linear-layer output (gather source)
__device__ float g_x[N_NODES * U];     // current activation
__device__ float g_as[N_NODES];
__device__ float g_ad[N_NODES];
__device__ float g_dinv[N_NODES];
__device__ int   g_deg[N_NODES];
__device__ int   g_rowtmp[N_NODES];
__device__ int   g_rowptr[N_NODES + 1];
__device__ int   g_cursor[N_NODES];
__device__ int   g_bsum[SCAN_NB];
__device__ int   g_csrc[E_TOT];        // CSR src list grouped by dst
__device__ float g_psum[2 * NG];
__device__ float g_pcnt[2 * NG];

// ---------------- helpers ----------------
__device__ __forceinline__ void edge_src_dst(int e, const int* __restrict__ ei,
                                             int& src, int& dst) {
    if (e < N_EDGES) { src = ei[e]; dst = ei[N_EDGES + e]; }
    else             { src = e - N_EDGES; dst = src; }
}

// ---------------- CSR build ----------------
__global__ void k_zero_deg() {
    int i = blockIdx.x * blockDim.x + threadIdx.x;
    if (i < N_NODES) g_deg[i] = 0;
}
__global__ void k_deg(const int* __restrict__ ei) {
    int e = blockIdx.x * blockDim.x + threadIdx.x;
    if (e >= E_TOT) return;
    int src, dst; edge_src_dst(e, ei, src, dst);
    atomicAdd(&g_deg[dst], 1);
}
__global__ void k_scan1() {   // per-block inclusive scan of degrees
    __shared__ int sm[SCAN_B];
    int t = threadIdx.x;
    int i = blockIdx.x * SCAN_B + t;
    int v = (i < N_NODES) ? g_deg[i] : 0;
    sm[t] = v;
    __syncthreads();
#pragma unroll
    for (int off = 1; off < SCAN_B; off <<= 1) {
        int add = (t >= off) ? sm[t - off] : 0;
        __syncthreads();
        sm[t] += add;
        __syncthreads();
    }
    if (i < N_NODES) g_rowtmp[i] = sm[t];
    if (t == SCAN_B - 1) g_bsum[blockIdx.x] = sm[t];
}
__global__ void k_scan2() {   // exclusive scan of block sums (tiny)
    if (threadIdx.x == 0) {
        int run = 0;
        for (int b = 0; b < SCAN_NB; b++) { int v = g_bsum[b]; g_bsum[b] = run; run += v; }
    }
}
__global__ void k_scan3() {   // finalize row_ptr, cursor, dinv
    int i = blockIdx.x * blockDim.x + threadIdx.x;
    if (i >= N_NODES) return;
    int incl = g_rowtmp[i] + g_bsum[i / SCAN_B];
    g_rowptr[i + 1] = incl;
    int d = g_deg[i];
    g_cursor[i] = incl - d;
    g_dinv[i] = rsqrtf((float)d);      // deg >= 1 (self loop)
    if (i == 0) g_rowptr[0] = 0;
}
__global__ void k_fill(const int* __restrict__ ei) {
    int e = blockIdx.x * blockDim.x + threadIdx.x;
    if (e >= E_TOT) return;
    int src, dst; edge_src_dst(e, ei, src, dst);
    int pos = atomicAdd(&g_cursor[dst], 1);
    g_csrc[pos] = src;
}

// ---------------- GAT linear + attention logits ----------------
__global__ void k_gat_lin(const float* __restrict__ x, const float* __restrict__ Wg,
                          const float* __restrict__ a_src, const float* __restrict__ a_dst) {
    __shared__ float Ws[F_IN * U];
    __shared__ float as_s[U], ad_s[U];
    int tid = threadIdx.x;
    for (int i = tid; i < F_IN * U; i += blockDim.x) Ws[i] = Wg[i];
    if (tid < U) { as_s[tid] = a_src[tid]; ad_s[tid] = a_dst[tid]; }
    __syncthreads();
    int lane = tid & 31, w = tid >> 5;
    int node = blockIdx.x * (blockDim.x >> 5) + w;
    if (node >= N_NODES) return;
    float acc0 = 0.f, acc1 = 0.f;
#pragma unroll
    for (int j = 0; j < F_IN; j++) {
        float v = __ldg(&x[node * F_IN + j]);   // broadcast across warp
        acc0 += v * Ws[j * U + lane];
        acc1 += v * Ws[j * U + lane + 32];
    }
    g_h[node * U + lane]      = acc0;
    g_h[node * U + lane + 32] = acc1;
    float s = acc0 * as_s[lane] + acc1 * as_s[lane + 32];
    float d = acc0 * ad_s[lane] + acc1 * ad_s[lane + 32];
#pragma unroll
    for (int o = 16; o > 0; o >>= 1) {
        s += __shfl_xor_sync(0xffffffffu, s, o);
        d += __shfl_xor_sync(0xffffffffu, d, o);
    }
    if (lane == 0) { g_as[node] = s; g_ad[node] = d; }
}

// ---------------- GAT gather: softmax over incoming edges + aggregate ----------------
__global__ void k_gat_gather(const float* __restrict__ b) {
    int lane = threadIdx.x & 31;
    int node = blockIdx.x * (blockDim.x >> 5) + (threadIdx.x >> 5);
    if (node >= N_NODES) return;
    int k0 = g_rowptr[node], k1 = g_rowptr[node + 1];
    float ad_n = g_ad[node];
    // pass 1: segment max (strided over lanes)
    float m = -3.4e38f;
    for (int k = k0 + lane; k < k1; k += 32) {
        float e = g_as[g_csrc[k]] + ad_n;
        e = e > 0.f ? e : 0.2f * e;
        m = fmaxf(m, e);
    }
#pragma unroll
    for (int o = 16; o > 0; o >>= 1) m = fmaxf(m, __shfl_xor_sync(0xffffffffu, m, o));
    // pass 2: exp-sum
    float ssum = 0.f;
    for (int k = k0 + lane; k < k1; k += 32) {
        float e = g_as[g_csrc[k]] + ad_n;
        e = e > 0.f ? e : 0.2f * e;
        ssum += __expf(e - m);
    }
#pragma unroll
    for (int o = 16; o > 0; o >>= 1) ssum += __shfl_xor_sync(0xffffffffu, ssum, o);
    float inv = 1.f / ssum;
    // pass 3: weighted feature gather (all lanes per slot; lane = channel)
    float acc0 = 0.f, acc1 = 0.f;
    int s_next = g_csrc[k0];
    for (int k = k0; k < k1; k++) {
        int s = s_next;
        if (k + 1 < k1) s_next = g_csrc[k + 1];
        float e = g_as[s] + ad_n;
        e = e > 0.f ? e : 0.2f * e;
        float cf = __expf(e - m) * inv;
        acc0 += cf * g_h[s * U + lane];
        acc1 += cf * g_h[s * U + lane + 32];
    }
    g_x[node * U + lane]      = tanhf(acc0 + b[lane]);
    g_x[node * U + lane + 32] = tanhf(acc1 + b[lane + 32]);
}

// ---------------- GCN gather: symmetric-norm aggregate + bias + tanh ----------------
__global__ void k_gcn_gather(const float* __restrict__ b) {
    int lane = threadIdx.x & 31;
    int node = blockIdx.x * (blockDim.x >> 5) + (threadIdx.x >> 5);
    if (node >= N_NODES) return;
    int k0 = g_rowptr[node], k1 = g_rowptr[node + 1];
    float dn = g_dinv[node];
    float acc0 = 0.f, acc1 = 0.f;
    int s_next = g_csrc[k0];
    for (int k = k0; k < k1; k++) {
        int s = s_next;
        if (k + 1 < k1) s_next = g_csrc[k + 1];
        float cf = g_dinv[s] * dn;
        acc0 += cf * g_h[s * U + lane];
        acc1 += cf * g_h[s * U + lane + 32];
    }
    g_x[node * U + lane]      = tanhf(acc0 + b[lane]);
    g_x[node * U + lane + 32] = tanhf(acc1 + b[lane + 32]);
}

// ---------------- 64x64 GEMM: g_h = g_x @ W ----------------
__global__ void k_gemm64(const float* __restrict__ W) {
    __shared__ float Ws[U * U];
    int tid = threadIdx.x;
    for (int i = tid; i < U * U; i += blockDim.x) Ws[i] = W[i];
    __syncthreads();
    int lane = tid & 31, w = tid >> 5;
    int base = (blockIdx.x * (blockDim.x >> 5) + w) * 4;
    if (base >= N_NODES) return;
    int nv = min(4, N_NODES - base);
    float xlo[4], xhi[4], a0[4] = {0,0,0,0}, a1[4] = {0,0,0,0};
#pragma unroll
    for (int n = 0; n < 4; n++) {
        int node = base + (n < nv ? n : 0);
        xlo[n] = g_x[node * U + lane];
        xhi[n] = g_x[node * U + lane + 32];
    }
#pragma unroll
    for (int k = 0; k < U; k++) {
        float w0 = Ws[k * U + lane], w1 = Ws[k * U + lane + 32];
#pragma unroll
        for (int n = 0; n < 4; n++) {
            float v = (k < 32) ? __shfl_sync(0xffffffffu, xlo[n], k)
                               : __shfl_sync(0xffffffffu, xhi[n], k - 32);
            a0[n] += v * w0;
            a1[n] += v * w1;
        }
    }
    for (int n = 0; n < nv; n++) {
        g_h[(base + n) * U + lane]      = a0[n];
        g_h[(base + n) * U + lane + 32] = a1[n];
    }
}

// ---------------- fused MLP (64->64->32->1) + mean-pool accumulate ----------------
__global__ void k_mlp_pool(const int* __restrict__ batch,
                           const float* __restrict__ W1, const float* __restrict__ b1,
                           const float* __restrict__ W2, const float* __restrict__ b2,
                           const float* __restrict__ W3, const float* __restrict__ b3,
                           int poff) {
    __shared__ float W1s[U * U], W2s[U * 32], b1s[U], b2s[32], W3s[32], b3s;
    int tid = threadIdx.x;
    for (int i = tid; i < U * U; i += blockDim.x)  W1s[i] = W1[i];
    for (int i = tid; i < U * 32; i += blockDim.x) W2s[i] = W2[i];
    if (tid < U)  b1s[tid] = b1[tid];
    if (tid < 32) { b2s[tid] = b2[tid]; W3s[tid] = W3[tid]; }
    if (tid == 0) b3s = b3[0];
    __syncthreads();
    int lane = tid & 31, w = tid >> 5;
    int node = blockIdx.x * (blockDim.x >> 5) + w;
    if (node >= N_NODES) return;
    float xlo = g_x[node * U + lane], xhi = g_x[node * U + lane + 32];
    float a0 = b1s[lane], a1 = b1s[lane + 32];
#pragma unroll
    for (int k = 0; k < U; k++) {
        float v = (k < 32) ? __shfl_sync(0xffffffffu, xlo, k)
                           : __shfl_sync(0xffffffffu, xhi, k - 32);
        a0 += v * W1s[k * U + lane];
        a1 += v * W1s[k * U + lane + 32];
    }
    float y1lo = tanhf(a0), y1hi = tanhf(a1);
    float a2 = b2s[lane];
#pragma unroll
    for (int k = 0; k < U; k++) {
        float v = (k < 32) ? __shfl_sync(0xffffffffu, y1lo, k)
                           : __shfl_sync(0xffffffffu, y1hi, k - 32);
        a2 += v * W2s[k * 32 + lane];
    }
    float y2 = tanhf(a2);
    float c = y2 * W3s[lane];
#pragma unroll
    for (int o = 16; o > 0; o >>= 1) c += __shfl_xor_sync(0xffffffffu, c, o);
    if (lane == 0) {
        float y = c + b3s;
        int g = batch[node];
        atomicAdd(&g_psum[poff + g], y);
        atomicAdd(&g_pcnt[poff + g], 1.0f);
    }
}

// ---------------- init pool + final ----------------
__global__ void k_init_pool() {
    int i = blockIdx.x * blockDim.x + threadIdx.x;
    if (i < 2 * NG) { g_psum[i] = 0.f; g_pcnt[i] = 0.f; }
}
__global__ void k_final(float* __restrict__ out) {
    int g = blockIdx.x * blockDim.x + threadIdx.x;
    if (g >= NG) return;
    float ua = g_psum[g]      / fmaxf(g_pcnt[g], 1.f);
    float ub = g_psum[NG + g] / fmaxf(g_pcnt[NG + g], 1.f);
    out[g] = 1.f / (1.f + expf(-(ub - ua)));
}

// ---------------- host orchestration ----------------
static void run_branch(const float* x, const int* ei, const int* batch,
                       const float* Wgat, const float* a_src, const float* a_dst, const float* bgat,
                       const float* Wgcn, const float* bgcn,
                       const float* W1, const float* b1, const float* W2, const float* b2,
                       const float* W3, const float* b3, int poff) {
    const int NB_N = (N_NODES + 255) / 256;
    const int NB_E = (E_TOT + 255) / 256;
    const int NB_W = (N_NODES + 7) / 8;      // 1 node per warp, 8 warps/block

    // CSR build
    k_zero_deg<<<NB_N, 256>>>();
    k_deg<<<NB_E, 256>>>(ei);
    k_scan1<<<SCAN_NB, SCAN_B>>>();
    k_scan2<<<1, 32>>>();
    k_scan3<<<NB_N, 256>>>();
    k_fill<<<NB_E, 256>>>(ei);
    // GAT
    k_gat_lin<<<NB_W, 256>>>(x, Wgat, a_src, a_dst);
    k_gat_gather<<<NB_W, 256>>>(bgat);
    // 2x GCN
    for (int l = 0; l < 2; l++) {
        k_gemm64<<<(N_NODES + 31) / 32, 256>>>(Wgcn + l * U * U);
        k_gcn_gather<<<NB_W, 256>>>(bgcn + l * U);
    }
    // MLP + pool
    k_mlp_pool<<<NB_W, 256>>>(batch, W1, b1, W2, b2, W3, b3, poff);
}

extern "C" void kernel_launch(void* const* d_in, const int* in_sizes, int n_in,
                              void* d_out, int out_size) {
    const float* x_a   = (const float*)d_in[0];
    const float* x_b   = (const float*)d_in[1];
    const int*   ei_a  = (const int*)  d_in[2];
    const int*   ei_b  = (const int*)  d_in[3];
    const int*   ba    = (const int*)  d_in[4];
    const int*   bb    = (const int*)  d_in[5];
    const float* Wgat  = (const float*)d_in[6];
    const float* a_src = (const float*)d_in[7];
    const float* a_dst = (const float*)d_in[8];
    const float* bgat  = (const float*)d_in[9];
    const float* Wgcn  = (const float*)d_in[10];
    const float* bgcn  = (const float*)d_in[11];
    const float* W1    = (const float*)d_in[12];
    const float* b1    = (const float*)d_in[13];
    const float* W2    = (const float*)d_in[14];
    const float* b2    = (const float*)d_in[15];
    const float* W3    = (const float*)d_in[16];
    const float* b3    = (const float*)d_in[17];

    k_init_pool<<<4, 256>>>();
    run_branch(x_a, ei_a, ba, Wgat, a_src, a_dst, bgat, Wgcn, bgcn,
               W1, b1, W2, b2, W3, b3, 0);
    run_branch(x_b, ei_b, bb, Wgat, a_src, a_dst, bgat, Wgcn, bgcn,
               W1, b1, W2, b2, W3, b3, NG);
    k_final<<<2, 256>>>((float*)d_out);
}

// round 3
// speedup vs baseline: 1.3342x; 1.0213x over previous
#include <cuda_runtime.h>
#include <math.h>

#define N_NODES 50000
#define N_EDGES 800000
#define E_TOT   850000   // edges + self loops
#define U       64
#define NG      512
#define F_IN    9
#define SCAN_B  1024
#define SCAN_NB ((N_NODES + SCAN_B - 1) / SCAN_B)   // 49
#define FULL    0xffffffffu

// ---------------- scratch (device globals; no allocations) ----------------
__device__ float g_bufA[2 * N_NODES * U];
__device__ float g_bufB[2 * N_NODES * U];
__device__ float g_as[2 * N_NODES];
__device__ float g_ad[2 * N_NODES];
__device__ float g_dinv[2 * N_NODES];
__device__ int   g_deg[2 * N_NODES];
__device__ int   g_rowtmp[2 * N_NODES];
__device__ int   g_rowptr[2 * (N_NODES + 1)];
__device__ int   g_cursor[2 * N_NODES];
__device__ int   g_bsum[2 * SCAN_NB];
__device__ int   g_csrc[2 * E_TOT];
__device__ float g_wa[F_IN], g_wd[F_IN];   // W @ a_src, W @ a_dst (9-dim)
__device__ float g_psum[2 * NG];
__device__ float g_pcnt[2 * NG];

__device__ __forceinline__ void edge_src_dst(int e, const int* __restrict__ ei,
                                             int& src, int& dst) {
    if (e < N_EDGES) { src = ei[e]; dst = ei[N_EDGES + e]; }
    else             { src = e - N_EDGES; dst = src; }
}

// ---------------- tiny precompute: wa = W@a_src, wd = W@a_dst ----------------
__global__ void k_wa(const float* __restrict__ W, const float* __restrict__ a_src,
                     const float* __restrict__ a_dst) {
    int t = threadIdx.x;
    if (t < F_IN) {
        float s = 0.f;
        for (int c = 0; c < U; c++) s += W[t * U + c] * a_src[c];
        g_wa[t] = s;
    } else if (t >= 16 && t < 16 + F_IN) {
        int f = t - 16;
        float s = 0.f;
        for (int c = 0; c < U; c++) s += W[f * U + c] * a_dst[c];
        g_wd[f] = s;
    }
}

// ---------------- CSR build (both branches per launch, br = blockIdx.y) ------
__global__ void k_zero_deg() {
    int i = blockIdx.x * blockDim.x + threadIdx.x;
    if (i < 2 * N_NODES) g_deg[i] = 0;
}
__global__ void k_deg(const int* __restrict__ ei_a, const int* __restrict__ ei_b) {
    int br = blockIdx.y;
    int e = blockIdx.x * blockDim.x + threadIdx.x;
    if (e >= E_TOT) return;
    const int* ei = br ? ei_b : ei_a;
    int src, dst; edge_src_dst(e, ei, src, dst);
    atomicAdd(&g_deg[br * N_NODES + dst], 1);
}
__global__ void k_scan1() {
    __shared__ int sm[SCAN_B];
    int br = blockIdx.y;
    int t = threadIdx.x;
    int i = blockIdx.x * SCAN_B + t;
    int v = (i < N_NODES) ? g_deg[br * N_NODES + i] : 0;
    sm[t] = v;
    __syncthreads();
#pragma unroll
    for (int off = 1; off < SCAN_B; off <<= 1) {
        int add = (t >= off) ? sm[t - off] : 0;
        __syncthreads();
        sm[t] += add;
        __syncthreads();
    }
    if (i < N_NODES) g_rowtmp[br * N_NODES + i] = sm[t];
    if (t == SCAN_B - 1) g_bsum[br * SCAN_NB + blockIdx.x] = sm[t];
}
__global__ void k_scan2() {
    int t = threadIdx.x;
    if (t < 2) {
        int run = 0;
        for (int b = 0; b < SCAN_NB; b++) {
            int v = g_bsum[t * SCAN_NB + b];
            g_bsum[t * SCAN_NB + b] = run;
            run += v;
        }
    }
}
__global__ void k_scan3(const float* __restrict__ xa, const float* __restrict__ xb) {
    int br = blockIdx.y;
    int i = blockIdx.x * blockDim.x + threadIdx.x;
    if (i >= N_NODES) return;
    int incl = g_rowtmp[br * N_NODES + i] + g_bsum[br * SCAN_NB + i / SCAN_B];
    int d = g_deg[br * N_NODES + i];
    g_rowptr[br * (N_NODES + 1) + i + 1] = incl;
    g_cursor[br * N_NODES + i] = incl - d;
    g_dinv[br * N_NODES + i] = rsqrtf((float)d);   // deg >= 1 (self loop)
    if (i == 0) g_rowptr[br * (N_NODES + 1)] = 0;
    // fused: attention logits as = x.(W a_src), ad = x.(W a_dst)
    const float* x = br ? xb : xa;
    const float* xi = x + i * F_IN;
    float as = 0.f, ad = 0.f;
#pragma unroll
    for (int f = 0; f < F_IN; f++) {
        float v = xi[f];
        as += v * g_wa[f];
        ad += v * g_wd[f];
    }
    g_as[br * N_NODES + i] = as;
    g_ad[br * N_NODES + i] = ad;
}
__global__ void k_fill(const int* __restrict__ ei_a, const int* __restrict__ ei_b) {
    int br = blockIdx.y;
    int e = blockIdx.x * blockDim.x + threadIdx.x;
    if (e >= E_TOT) return;
    const int* ei = br ? ei_b : ei_a;
    int src, dst; edge_src_dst(e, ei, src, dst);
    int pos = atomicAdd(&g_cursor[br * N_NODES + dst], 1);
    g_csrc[br * E_TOT + pos] = src;
}

// ---------------- GAT: softmax-weighted aggregate of RAW x, then @W ----------
__global__ void k_gat_gather(const float* __restrict__ xa, const float* __restrict__ xb,
                             const float* __restrict__ W, const float* __restrict__ b) {
    __shared__ float Ws[F_IN * U];
    __shared__ float bs[U];
    int tid = threadIdx.x;
    for (int i = tid; i < F_IN * U; i += blockDim.x) Ws[i] = W[i];
    if (tid < U) bs[tid] = b[tid];
    __syncthreads();
    int br = blockIdx.y;
    int lane = tid & 31;
    int node = blockIdx.x * (blockDim.x >> 5) + (tid >> 5);
    if (node >= N_NODES) return;
    const float* x = br ? xb : xa;
    const int*   csrc = g_csrc + br * E_TOT;
    const int*   rp   = g_rowptr + br * (N_NODES + 1);
    const float* as   = g_as + br * N_NODES;
    int k0 = rp[node], k1 = rp[node + 1];
    float ad_n = g_ad[br * N_NODES + node];
    // single pass: unnormalized exp weights + weighted 9-dim aggregate
    float acc[F_IN] = {0, 0, 0, 0, 0, 0, 0, 0, 0};
    float ssum = 0.f;
    for (int k = k0 + lane; k < k1; k += 32) {
        int s = csrc[k];
        float e = as[s] + ad_n;
        e = e > 0.f ? e : 0.2f * e;
        float ex = __expf(e);   // logits bounded; ratio cancels any scaling
        ssum += ex;
        const float* xs = x + s * F_IN;
#pragma unroll
        for (int f = 0; f < F_IN; f++) acc[f] += ex * xs[f];
    }
#pragma unroll
    for (int o = 16; o > 0; o >>= 1) {
        ssum += __shfl_xor_sync(FULL, ssum, o);
#pragma unroll
        for (int f = 0; f < F_IN; f++) acc[f] += __shfl_xor_sync(FULL, acc[f], o);
    }
    float inv = 1.f / ssum;
    // epilogue: y = (agg/ssum) @ W + b, tanh; lane -> channels {2l, 2l+1}
    int c0 = 2 * lane;
    float y0 = bs[c0], y1 = bs[c0 + 1];
#pragma unroll
    for (int f = 0; f < F_IN; f++) {
        float v = acc[f] * inv;
        y0 += v * Ws[f * U + c0];
        y1 += v * Ws[f * U + c0 + 1];
    }
    float2 o2; o2.x = tanhf(y0); o2.y = tanhf(y1);
    reinterpret_cast<float2*>(g_bufA + (size_t)br * N_NODES * U)[node * 32 + lane] = o2;
}

// ---------------- GCN: norm-weighted aggregate, then @W + b, tanh ------------
__global__ void k_gcn_gather(int dir, const float* __restrict__ W, const float* __restrict__ b) {
    __shared__ float Ws[U * U];
    __shared__ float bs[U];
    int tid = threadIdx.x;
    for (int i = tid; i < U * U; i += blockDim.x) Ws[i] = W[i];
    if (tid < U) bs[tid] = b[tid];
    __syncthreads();
    int br = blockIdx.y;
    int lane = tid & 31;
    int node = blockIdx.x * (blockDim.x >> 5) + (tid >> 5);
    if (node >= N_NODES) return;
    const float* in  = dir ? g_bufB : g_bufA;
    float*       out = dir ? g_bufA : g_bufB;
    const float2* x2 = reinterpret_cast<const float2*>(in + (size_t)br * N_NODES * U);
    const int*   csrc = g_csrc + br * E_TOT;
    const int*   rp   = g_rowptr + br * (N_NODES + 1);
    const float* dinv = g_dinv + br * N_NODES;
    int k0 = rp[node], k1 = rp[node + 1];
    float dn = dinv[node];
    float ax = 0.f, ay = 0.f;
    for (int kk = k0; kk < k1; kk += 32) {
        int cnt = min(32, k1 - kk);
        int s_l = 0; float d_l = 0.f;
        if (lane < cnt) { s_l = csrc[kk + lane]; d_l = dinv[s_l]; }
#pragma unroll 4
        for (int j = 0; j < cnt; j++) {
            int   s  = __shfl_sync(FULL, s_l, j);
            float cf = __shfl_sync(FULL, d_l, j) * dn;
            float2 v = x2[s * 32 + lane];
            ax += cf * v.x;
            ay += cf * v.y;
        }
    }
    // in-warp GEMV: y[c] = sum_k agg[k] * W[k][c]; agg held 2 ch/lane
    const float2* Ws2 = reinterpret_cast<const float2*>(Ws);
    float y0 = bs[2 * lane], y1 = bs[2 * lane + 1];
#pragma unroll
    for (int k = 0; k < U; k++) {
        float v = __shfl_sync(FULL, (k & 1) ? ay : ax, k >> 1);
        float2 w = Ws2[k * 32 + lane];
        y0 += v * w.x;
        y1 += v * w.y;
    }
    float2 o2; o2.x = tanhf(y0); o2.y = tanhf(y1);
    reinterpret_cast<float2*>(out + (size_t)br * N_NODES * U)[node * 32 + lane] = o2;
}

// ---------------- fused MLP (64->64->32->1) + mean-pool accumulate ----------
__global__ void k_mlp_pool(const int* __restrict__ ba, const int* __restrict__ bb,
                           const float* __restrict__ W1, const float* __restrict__ b1,
                           const float* __restrict__ W2, const float* __restrict__ b2,
                           const float* __restrict__ W3, const float* __restrict__ b3) {
    __shared__ float W1s[U * U], W2s[U * 32], b1s[U], b2s[32], W3s[32], b3s;
    int tid = threadIdx.x;
    for (int i = tid; i < U * U; i += blockDim.x)  W1s[i] = W1[i];
    for (int i = tid; i < U * 32; i += blockDim.x) W2s[i] = W2[i];
    if (tid < U)  b1s[tid] = b1[tid];
    if (tid < 32) { b2s[tid] = b2[tid]; W3s[tid] = W3[tid]; }
    if (tid == 0) b3s = b3[0];
    __syncthreads();
    int br = blockIdx.y;
    int lane = tid & 31;
    int node = blockIdx.x * (blockDim.x >> 5) + (tid >> 5);
    if (node >= N_NODES) return;
    const float* xp = g_bufA + (size_t)br * N_NODES * U;
    float xlo = xp[node * U + lane], xhi = xp[node * U + lane + 32];
    float a0 = b1s[lane], a1 = b1s[lane + 32];
#pragma unroll
    for (int k = 0; k < U; k++) {
        float v = (k < 32) ? __shfl_sync(FULL, xlo, k)
                           : __shfl_sync(FULL, xhi, k - 32);
        a0 += v * W1s[k * U + lane];
        a1 += v * W1s[k * U + lane + 32];
    }
    float y1lo = tanhf(a0), y1hi = tanhf(a1);
    float a2 = b2s[lane];
#pragma unroll
    for (int k = 0; k < U; k++) {
        float v = (k < 32) ? __shfl_sync(FULL, y1lo, k)
                           : __shfl_sync(FULL, y1hi, k - 32);
        a2 += v * W2s[k * 32 + lane];
    }
    float y2 = tanhf(a2);
    float c = y2 * W3s[lane];
#pragma unroll
    for (int o = 16; o > 0; o >>= 1) c += __shfl_xor_sync(FULL, c, o);
    if (lane == 0) {
        const int* batch = br ? bb : ba;
        int g = batch[node];
        atomicAdd(&g_psum[br * NG + g], c + b3s);
        atomicAdd(&g_pcnt[br * NG + g], 1.0f);
    }
}

// ---------------- init pool + final ----------------
__global__ void k_init_pool() {
    int i = blockIdx.x * blockDim.x + threadIdx.x;
    if (i < 2 * NG) { g_psum[i] = 0.f; g_pcnt[i] = 0.f; }
}
__global__ void k_final(float* __restrict__ out) {
    int g = blockIdx.x * blockDim.x + threadIdx.x;
    if (g >= NG) return;
    float ua = g_psum[g]      / fmaxf(g_pcnt[g], 1.f);
    float ub = g_psum[NG + g] / fmaxf(g_pcnt[NG + g], 1.f);
    out[g] = 1.f / (1.f + expf(-(ub - ua)));
}

// ---------------- host orchestration ----------------
extern "C" void kernel_launch(void* const* d_in, const int* in_sizes, int n_in,
                              void* d_out, int out_size) {
    const float* x_a   = (const float*)d_in[0];
    const float* x_b   = (const float*)d_in[1];
    const int*   ei_a  = (const int*)  d_in[2];
    const int*   ei_b  = (const int*)  d_in[3];
    const int*   ba    = (const int*)  d_in[4];
    const int*   bb    = (const int*)  d_in[5];
    const float* Wgat  = (const float*)d_in[6];
    const float* a_src = (const float*)d_in[7];
    const float* a_dst = (const float*)d_in[8];
    const float* bgat  = (const float*)d_in[9];
    const float* Wgcn  = (const float*)d_in[10];
    const float* bgcn  = (const float*)d_in[11];
    const float* W1    = (const float*)d_in[12];
    const float* b1    = (const float*)d_in[13];
    const float* W2    = (const float*)d_in[14];
    const float* b2    = (const float*)d_in[15];
    const float* W3    = (const float*)d_in[16];
    const float* b3    = (const float*)d_in[17];

    dim3 gE((E_TOT + 255) / 256, 2);
    dim3 gS(SCAN_NB, 2);
    dim3 gN((N_NODES + 255) / 256, 2);
    dim3 gW((N_NODES + 7) / 8, 2);    // 1 node per warp, 8 warps/block

    k_init_pool<<<4, 256>>>();
    k_wa<<<1, 32>>>(Wgat, a_src, a_dst);
    k_zero_deg<<<(2 * N_NODES + 255) / 256, 256>>>();
    k_deg<<<gE, 256>>>(ei_a, ei_b);
    k_scan1<<<gS, SCAN_B>>>();
    k_scan2<<<1, 32>>>();
    k_scan3<<<gN, 256>>>(x_a, x_b);
    k_fill<<<gE, 256>>>(ei_a, ei_b);
    k_gat_gather<<<gW, 256>>>(x_a, x_b, Wgat, bgat);
    k_gcn_gather<<<gW, 256>>>(0, Wgcn, bgcn);              // bufA -> bufB
    k_gcn_gather<<<gW, 256>>>(1, Wgcn + U * U, bgcn + U);  // bufB -> bufA
    k_mlp_pool<<<gW, 256>>>(ba, bb, W1, b1, W2, b2, W3, b3);
    k_final<<<2, 256>>>((float*)d_out);
}

// round 6
// speedup vs baseline: 1.4331x; 1.0742x over previous
#include <cuda_runtime.h>
#include <cuda_fp16.h>
#include <math.h>

#define N_NODES 50000
#define N_EDGES 800000
#define E_TOT   850000   // edges + self loops
#define U       64
#define NG      512
#define F_IN    9
#define SCAN_B  1024
#define SCAN_NB ((N_NODES + SCAN_B - 1) / SCAN_B)   // 49
#define FULL    0xffffffffu

// ---------------- scratch (device globals; no allocations) ----------------
__device__ __half g_bufA[2 * N_NODES * U];   // fp16 feature storage
__device__ __half g_bufB[2 * N_NODES * U];
__device__ float  g_as[2 * N_NODES];
__device__ float  g_ad[2 * N_NODES];
__device__ float  g_dinv[2 * N_NODES];
__device__ int    g_deg[2 * N_NODES];
__device__ int    g_rowtmp[2 * N_NODES];
__device__ int    g_rowptr[2 * (N_NODES + 1)];
__device__ int    g_cursor[2 * N_NODES];
__device__ int    g_bsum[2 * SCAN_NB];
__device__ int    g_csrc[2 * E_TOT];
__device__ float  g_wa[F_IN], g_wd[F_IN];    // W @ a_src, W @ a_dst
__device__ float  g_psum[2 * NG];
__device__ float  g_pcnt[2 * NG];

__device__ __forceinline__ void edge_src_dst(int e, const int* __restrict__ ei,
                                             int& src, int& dst) {
    if (e < N_EDGES) { src = ei[e]; dst = ei[N_EDGES + e]; }
    else             { src = e - N_EDGES; dst = src; }
}

// ---------------- pre: zero deg + pool, compute wa/wd ----------------
__global__ void k_pre(const float* __restrict__ W, const float* __restrict__ a_src,
                      const float* __restrict__ a_dst) {
    int i = blockIdx.x * blockDim.x + threadIdx.x;
    if (i < 2 * N_NODES) g_deg[i] = 0;
    if (i < 2 * NG) { g_psum[i] = 0.f; g_pcnt[i] = 0.f; }
    if (blockIdx.x == 0) {
        int t = threadIdx.x;
        if (t < F_IN) {
            float s = 0.f;
            for (int c = 0; c < U; c++) s += W[t * U + c] * a_src[c];
            g_wa[t] = s;
        } else if (t >= 16 && t < 16 + F_IN) {
            int f = t - 16;
            float s = 0.f;
            for (int c = 0; c < U; c++) s += W[f * U + c] * a_dst[c];
            g_wd[f] = s;
        }
    }
}

// ---------------- CSR build (br = blockIdx.y) ----------------
__global__ void k_deg(const int* __restrict__ ei_a, const int* __restrict__ ei_b) {
    int br = blockIdx.y;
    int e = blockIdx.x * blockDim.x + threadIdx.x;
    if (e >= E_TOT) return;
    const int* ei = br ? ei_b : ei_a;
    int src, dst; edge_src_dst(e, ei, src, dst);
    atomicAdd(&g_deg[br * N_NODES + dst], 1);
}
__global__ void k_scan1() {
    __shared__ int sm[SCAN_B];
    int br = blockIdx.y;
    int t = threadIdx.x;
    int i = blockIdx.x * SCAN_B + t;
    int v = (i < N_NODES) ? g_deg[br * N_NODES + i] : 0;
    sm[t] = v;
    __syncthreads();
#pragma unroll
    for (int off = 1; off < SCAN_B; off <<= 1) {
        int add = (t >= off) ? sm[t - off] : 0;
        __syncthreads();
        sm[t] += add;
        __syncthreads();
    }
    if (i < N_NODES) g_rowtmp[br * N_NODES + i] = sm[t];
    if (t == SCAN_B - 1) g_bsum[br * SCAN_NB + blockIdx.x] = sm[t];
}
// scan3: inline exclusive prefix over the 49 block sums + fused logits
__global__ void k_scan3(const float* __restrict__ xa, const float* __restrict__ xb) {
    __shared__ int bsm[SCAN_NB];
    int br = blockIdx.y;
    int t = threadIdx.x;
    if (t < SCAN_NB) bsm[t] = g_bsum[br * SCAN_NB + t];
    __syncthreads();
    int i = blockIdx.x * blockDim.x + t;
    if (i >= N_NODES) return;
    int blk = i / SCAN_B;
    int pre = 0;
    for (int b = 0; b < blk; b++) pre += bsm[b];
    int incl = g_rowtmp[br * N_NODES + i] + pre;
    int d = g_deg[br * N_NODES + i];
    g_rowptr[br * (N_NODES + 1) + i + 1] = incl;
    g_cursor[br * N_NODES + i] = incl - d;
    g_dinv[br * N_NODES + i] = rsqrtf((float)d);   // deg >= 1 (self loop)
    if (i == 0) g_rowptr[br * (N_NODES + 1)] = 0;
    const float* x = br ? xb : xa;
    const float* xi = x + i * F_IN;
    float as = 0.f, ad = 0.f;
#pragma unroll
    for (int f = 0; f < F_IN; f++) {
        float v = xi[f];
        as += v * g_wa[f];
        ad += v * g_wd[f];
    }
    g_as[br * N_NODES + i] = as;
    g_ad[br * N_NODES + i] = ad;
}
__global__ void k_fill(const int* __restrict__ ei_a, const int* __restrict__ ei_b) {
    int br = blockIdx.y;
    int e = blockIdx.x * blockDim.x + threadIdx.x;
    if (e >= E_TOT) return;
    const int* ei = br ? ei_b : ei_a;
    int src, dst; edge_src_dst(e, ei, src, dst);
    int pos = atomicAdd(&g_cursor[br * N_NODES + dst], 1);
    g_csrc[br * E_TOT + pos] = src;
}

// ---------------- GAT: softmax-weighted aggregate of raw x, then @W ----------
__global__ void k_gat_gather(const float* __restrict__ xa, const float* __restrict__ xb,
                             const float* __restrict__ W, const float* __restrict__ b) {
    __shared__ float Ws[F_IN * U];
    __shared__ float bs[U];
    int tid = threadIdx.x;
    for (int i = tid; i < F_IN * U; i += blockDim.x) Ws[i] = W[i];
    if (tid < U) bs[tid] = b[tid];
    __syncthreads();
    int br = blockIdx.y;
    int lane = tid & 31;
    int node = blockIdx.x * (blockDim.x >> 5) + (tid >> 5);
    if (node >= N_NODES) return;
    const float* x = br ? xb : xa;
    const int*   csrc = g_csrc + br * E_TOT;
    const int*   rp   = g_rowptr + br * (N_NODES + 1);
    const float* as   = g_as + br * N_NODES;
    int k0 = rp[node], k1 = rp[node + 1];
    float ad_n = g_ad[br * N_NODES + node];
    float acc[F_IN] = {0, 0, 0, 0, 0, 0, 0, 0, 0};
    float ssum = 0.f;
    for (int k = k0 + lane; k < k1; k += 32) {
        int s = csrc[k];
        float e = as[s] + ad_n;
        e = e > 0.f ? e : 0.2f * e;
        e = fminf(e, 80.f);     // overflow guard; inert for this data
        float ex = __expf(e);   // unnormalized; ratio cancels scaling
        ssum += ex;
        const float* xs = x + s * F_IN;
#pragma unroll
        for (int f = 0; f < F_IN; f++) acc[f] += ex * xs[f];
    }
#pragma unroll
    for (int o = 16; o > 0; o >>= 1) {
        ssum += __shfl_xor_sync(FULL, ssum, o);
#pragma unroll
        for (int f = 0; f < F_IN; f++) acc[f] += __shfl_xor_sync(FULL, acc[f], o);
    }
    float inv = 1.f / ssum;
    int c0 = 2 * lane;
    float y0 = bs[c0], y1 = bs[c0 + 1];
#pragma unroll
    for (int f = 0; f < F_IN; f++) {
        float v = acc[f] * inv;
        y0 += v * Ws[f * U + c0];
        y1 += v * Ws[f * U + c0 + 1];
    }
    __half2* out2 = reinterpret_cast<__half2*>(g_bufA) + (size_t)br * N_NODES * 32;
    out2[node * 32 + lane] = __floats2half2_rn(tanhf(y0), tanhf(y1));
}

// ---------------- GCN layer 1: bufA -> bufB ----------------
__global__ void k_gcn1(const float* __restrict__ W, const float* __restrict__ b) {
    __shared__ float Ws[U * U];
    __shared__ float bs[U];
    int tid = threadIdx.x;
    for (int i = tid; i < U * U; i += blockDim.x) Ws[i] = W[i];
    if (tid < U) bs[tid] = b[tid];
    __syncthreads();
    int br = blockIdx.y;
    int lane = tid & 31;
    int node = blockIdx.x * (blockDim.x >> 5) + (tid >> 5);
    if (node >= N_NODES) return;
    const __half2* x2 = reinterpret_cast<const __half2*>(g_bufA) + (size_t)br * N_NODES * 32;
    const int*   csrc = g_csrc + br * E_TOT;
    const int*   rp   = g_rowptr + br * (N_NODES + 1);
    const float* dinv = g_dinv + br * N_NODES;
    int k0 = rp[node], k1 = rp[node + 1];
    float dn = dinv[node];
    float ax = 0.f, ay = 0.f;
    for (int kk = k0; kk < k1; kk += 32) {
        int cnt = min(32, k1 - kk);
        int s_l = 0; float d_l = 0.f;
        if (lane < cnt) { s_l = csrc[kk + lane]; d_l = dinv[s_l]; }
#pragma unroll 4
        for (int j = 0; j < cnt; j++) {
            int   s  = __shfl_sync(FULL, s_l, j);
            float cf = __shfl_sync(FULL, d_l, j) * dn;
            float2 v = __half22float2(x2[s * 32 + lane]);
            ax += cf * v.x;
            ay += cf * v.y;
        }
    }
    const float2* Ws2 = reinterpret_cast<const float2*>(Ws);
    float y0 = bs[2 * lane], y1 = bs[2 * lane + 1];
#pragma unroll
    for (int k = 0; k < U; k++) {
        float v = __shfl_sync(FULL, (k & 1) ? ay : ax, k >> 1);
        float2 w = Ws2[k * 32 + lane];
        y0 += v * w.x;
        y1 += v * w.y;
    }
    __half2* out2 = reinterpret_cast<__half2*>(g_bufB) + (size_t)br * N_NODES * 32;
    out2[node * 32 + lane] = __floats2half2_rn(tanhf(y0), tanhf(y1));
}

// ---------------- GCN layer 2 + MLP + mean-pool, fused ----------------
__global__ void k_gcn2_mlp(const float* __restrict__ W, const float* __restrict__ b,
                           const int* __restrict__ ba, const int* __restrict__ bb,
                           const float* __restrict__ W1, const float* __restrict__ b1,
                           const float* __restrict__ W2, const float* __restrict__ b2,
                           const float* __restrict__ W3, const float* __restrict__ b3) {
    __shared__ float Ws[U * U], W1s[U * U], W2s[U * 32];
    __shared__ float bs[U], b1s[U], b2s[32], W3s[32], b3s;
    int tid = threadIdx.x;
    for (int i = tid; i < U * U; i += blockDim.x)  { Ws[i] = W[i]; W1s[i] = W1[i]; }
    for (int i = tid; i < U * 32; i += blockDim.x) W2s[i] = W2[i];
    if (tid < U)  { bs[tid] = b[tid]; b1s[tid] = b1[tid]; }
    if (tid < 32) { b2s[tid] = b2[tid]; W3s[tid] = W3[tid]; }
    if (tid == 0) b3s = b3[0];
    __syncthreads();
    int br = blockIdx.y;
    int lane = tid & 31;
    int node = blockIdx.x * (blockDim.x >> 5) + (tid >> 5);
    if (node >= N_NODES) return;
    const __half2* x2 = reinterpret_cast<const __half2*>(g_bufB) + (size_t)br * N_NODES * 32;
    const int*   csrc = g_csrc + br * E_TOT;
    const int*   rp   = g_rowptr + br * (N_NODES + 1);
    const float* dinv = g_dinv + br * N_NODES;
    int k0 = rp[node], k1 = rp[node + 1];
    float dn = dinv[node];
    float ax = 0.f, ay = 0.f;
    for (int kk = k0; kk < k1; kk += 32) {
        int cnt = min(32, k1 - kk);
        int s_l = 0; float d_l = 0.f;
        if (lane < cnt) { s_l = csrc[kk + lane]; d_l = dinv[s_l]; }
#pragma unroll 4
        for (int j = 0; j < cnt; j++) {
            int   s  = __shfl_sync(FULL, s_l, j);
            float cf = __shfl_sync(FULL, d_l, j) * dn;
            float2 v = __half22float2(x2[s * 32 + lane]);
            ax += cf * v.x;
            ay += cf * v.y;
        }
    }
    // GCN epilogue GEMV (channels 2l, 2l+1)
    const float2* Ws2 = reinterpret_cast<const float2*>(Ws);
    float y0 = bs[2 * lane], y1 = bs[2 * lane + 1];
#pragma unroll
    for (int k = 0; k < U; k++) {
        float v = __shfl_sync(FULL, (k & 1) ? ay : ax, k >> 1);
        float2 w = Ws2[k * 32 + lane];
        y0 += v * w.x;
        y1 += v * w.y;
    }
    y0 = tanhf(y0); y1 = tanhf(y1);
    // MLP layer1 (64->64)
    const float2* W1s2 = reinterpret_cast<const float2*>(W1s);
    float a0 = b1s[2 * lane], a1 = b1s[2 * lane + 1];
#pragma unroll
    for (int k = 0; k < U; k++) {
        float v = __shfl_sync(FULL, (k & 1) ? y1 : y0, k >> 1);
        float2 w = W1s2[k * 32 + lane];
        a0 += v * w.x;
        a1 += v * w.y;
    }
    float z0 = tanhf(a0), z1 = tanhf(a1);
    // MLP layer2 (64->32)
    float a2 = b2s[lane];
#pragma unroll
    for (int k = 0; k < U; k++) {
        float v = __shfl_sync(FULL, (k & 1) ? z1 : z0, k >> 1);
        a2 += v * W2s[k * 32 + lane];
    }
    float y2 = tanhf(a2);
    // MLP layer3 (32->1) + warp reduce + pool
    float c = y2 * W3s[lane];
#pragma unroll
    for (int o = 16; o > 0; o >>= 1) c += __shfl_xor_sync(FULL, c, o);
    if (lane == 0) {
        const int* batch = br ? bb : ba;
        int g = batch[node];
        atomicAdd(&g_psum[br * NG + g], c + b3s);
        atomicAdd(&g_pcnt[br * NG + g], 1.0f);
    }
}

// ---------------- final ----------------
__global__ void k_final(float* __restrict__ out) {
    int g = blockIdx.x * blockDim.x + threadIdx.x;
    if (g >= NG) return;
    float ua = g_psum[g]      / fmaxf(g_pcnt[g], 1.f);
    float ub = g_psum[NG + g] / fmaxf(g_pcnt[NG + g], 1.f);
    out[g] = 1.f / (1.f + expf(-(ub - ua)));
}

// ---------------- host orchestration ----------------
extern "C" void kernel_launch(void* const* d_in, const int* in_sizes, int n_in,
                              void* d_out, int out_size) {
    const float* x_a   = (const float*)d_in[0];
    const float* x_b   = (const float*)d_in[1];
    const int*   ei_a  = (const int*)  d_in[2];
    const int*   ei_b  = (const int*)  d_in[3];
    const int*   ba    = (const int*)  d_in[4];
    const int*   bb    = (const int*)  d_in[5];
    const float* Wgat  = (const float*)d_in[6];
    const float* a_src = (const float*)d_in[7];
    const float* a_dst = (const float*)d_in[8];
    const float* bgat  = (const float*)d_in[9];
    const float* Wgcn  = (const float*)d_in[10];
    const float* bgcn  = (const float*)d_in[11];
    const float* W1    = (const float*)d_in[12];
    const float* b1    = (const float*)d_in[13];
    const float* W2    = (const float*)d_in[14];
    const float* b2    = (const float*)d_in[15];
    const float* W3    = (const float*)d_in[16];
    const float* b3    = (const float*)d_in[17];

    dim3 gE((E_TOT + 255) / 256, 2);
    dim3 gS(SCAN_NB, 2);
    dim3 gN((N_NODES + 255) / 256, 2);
    dim3 gW((N_NODES + 7) / 8, 2);    // 1 node per warp, 8 warps/block

    k_pre<<<(2 * N_NODES + 255) / 256, 256>>>(Wgat, a_src, a_dst);
    k_deg<<<gE, 256>>>(ei_a, ei_b);
    k_scan1<<<gS, SCAN_B>>>();
    k_scan3<<<gN, 256>>>(x_a, x_b);
    k_fill<<<gE, 256>>>(ei_a, ei_b);
    k_gat_gather<<<gW, 256>>>(x_a, x_b, Wgat, bgat);
    k_gcn1<<<gW, 256>>>(Wgcn, bgcn);
    k_gcn2_mlp<<<gW, 256>>>(Wgcn + U * U, bgcn + U, ba, bb,
                            W1, b1, W2, b2, W3, b3);
    k_final<<<2, 256>>>((float*)d_out);
}

// round 9
// speedup vs baseline: 1.6825x; 1.1740x over previous
#include <cuda_runtime.h>
#include <cuda_fp16.h>
#include <math.h>

#define N_NODES 50000
#define N_EDGES 800000
#define E_TOT   850000   // edges + self loops
#define U       64
#define NG      512
#define F_IN    9
#define SCAN_B  1024
#define SCAN_NB ((N_NODES + SCAN_B - 1) / SCAN_B)   // 49
#define FULL    0xffffffffu

// ---------------- scratch (device globals; no allocations) ----------------
__device__ uint2  g_bufA[2 * N_NODES * 16];   // fp16 features, 64 half per node
__device__ uint2  g_bufB[2 * N_NODES * 16];
__device__ float  g_as[2 * N_NODES];
__device__ float  g_ad[2 * N_NODES];
__device__ float  g_dinv[2 * N_NODES];
__device__ int    g_deg[2 * N_NODES];
__device__ int    g_rowtmp[2 * N_NODES];
__device__ int    g_rowptr[2 * (N_NODES + 1)];
__device__ int    g_cursor[2 * N_NODES];
__device__ int    g_bsum[2 * SCAN_NB];
__device__ int    g_csrc[2 * E_TOT];
__device__ float  g_wa[F_IN], g_wd[F_IN];
__device__ float  g_psum[2 * NG];
__device__ float  g_pcnt[2 * NG];

__device__ __forceinline__ void edge_src_dst(int e, const int* __restrict__ ei,
                                             int& src, int& dst) {
    if (e < N_EDGES) { src = ei[e]; dst = ei[N_EDGES + e]; }
    else             { src = e - N_EDGES; dst = src; }
}

// ---------------- pre: zero deg + pool, compute wa/wd ----------------
__global__ void k_pre(const float* __restrict__ W, const float* __restrict__ a_src,
                      const float* __restrict__ a_dst) {
    int i = blockIdx.x * blockDim.x + threadIdx.x;
    if (i < 2 * N_NODES) g_deg[i] = 0;
    if (i < 2 * NG) { g_psum[i] = 0.f; g_pcnt[i] = 0.f; }
    if (blockIdx.x == 0) {
        int t = threadIdx.x;
        if (t < F_IN) {
            float s = 0.f;
            for (int c = 0; c < U; c++) s += W[t * U + c] * a_src[c];
            g_wa[t] = s;
        } else if (t >= 16 && t < 16 + F_IN) {
            int f = t - 16;
            float s = 0.f;
            for (int c = 0; c < U; c++) s += W[f * U + c] * a_dst[c];
            g_wd[f] = s;
        }
    }
}

// ---------------- CSR build ----------------
__global__ void k_deg(const int* __restrict__ ei_a, const int* __restrict__ ei_b) {
    int br = blockIdx.y;
    int e = blockIdx.x * blockDim.x + threadIdx.x;
    if (e >= E_TOT) return;
    const int* ei = br ? ei_b : ei_a;
    int src, dst; edge_src_dst(e, ei, src, dst);
    atomicAdd(&g_deg[br * N_NODES + dst], 1);
}
__global__ void k_scan1() {
    __shared__ int sm[SCAN_B];
    int br = blockIdx.y;
    int t = threadIdx.x;
    int i = blockIdx.x * SCAN_B + t;
    int v = (i < N_NODES) ? g_deg[br * N_NODES + i] : 0;
    sm[t] = v;
    __syncthreads();
#pragma unroll
    for (int off = 1; off < SCAN_B; off <<= 1) {
        int add = (t >= off) ? sm[t - off] : 0;
        __syncthreads();
        sm[t] += add;
        __syncthreads();
    }
    if (i < N_NODES) g_rowtmp[br * N_NODES + i] = sm[t];
    if (t == SCAN_B - 1) g_bsum[br * SCAN_NB + blockIdx.x] = sm[t];
}
__global__ void k_scan3(const float* __restrict__ xa, const float* __restrict__ xb) {
    __shared__ int bsm[SCAN_NB];
    int br = blockIdx.y;
    int t = threadIdx.x;
    if (t < SCAN_NB) bsm[t] = g_bsum[br * SCAN_NB + t];
    __syncthreads();
    int i = blockIdx.x * blockDim.x + t;
    if (i >= N_NODES) return;
    int blk = i / SCAN_B;
    int pre = 0;
    for (int b = 0; b < blk; b++) pre += bsm[b];
    int incl = g_rowtmp[br * N_NODES + i] + pre;
    int d = g_deg[br * N_NODES + i];
    g_rowptr[br * (N_NODES + 1) + i + 1] = incl;
    g_cursor[br * N_NODES + i] = incl - d;
    g_dinv[br * N_NODES + i] = rsqrtf((float)d);
    if (i == 0) g_rowptr[br * (N_NODES + 1)] = 0;
    const float* x = br ? xb : xa;
    const float* xi = x + i * F_IN;
    float as = 0.f, ad = 0.f;
#pragma unroll
    for (int f = 0; f < F_IN; f++) {
        float v = xi[f];
        as += v * g_wa[f];
        ad += v * g_wd[f];
    }
    g_as[br * N_NODES + i] = as;
    g_ad[br * N_NODES + i] = ad;
}
__global__ void k_fill(const int* __restrict__ ei_a, const int* __restrict__ ei_b) {
    int br = blockIdx.y;
    int e = blockIdx.x * blockDim.x + threadIdx.x;
    if (e >= E_TOT) return;
    const int* ei = br ? ei_b : ei_a;
    int src, dst; edge_src_dst(e, ei, src, dst);
    int pos = atomicAdd(&g_cursor[br * N_NODES + dst], 1);
    g_csrc[br * E_TOT + pos] = src;
}

// ---------------- GAT: softmax-weighted aggregate of raw x, then @W ----------
__global__ void k_gat_gather(const float* __restrict__ xa, const float* __restrict__ xb,
                             const float* __restrict__ W, const float* __restrict__ b) {
    __shared__ float Ws[F_IN * U];
    __shared__ float bs[U];
    int tid = threadIdx.x;
    for (int i = tid; i < F_IN * U; i += blockDim.x) Ws[i] = W[i];
    if (tid < U) bs[tid] = b[tid];
    __syncthreads();
    int br = blockIdx.y;
    int lane = tid & 31;
    int node = blockIdx.x * (blockDim.x >> 5) + (tid >> 5);
    if (node >= N_NODES) return;
    const float* x = br ? xb : xa;
    const int*   csrc = g_csrc + br * E_TOT;
    const int*   rp   = g_rowptr + br * (N_NODES + 1);
    const float* as   = g_as + br * N_NODES;
    int k0 = rp[node], k1 = rp[node + 1];
    float ad_n = g_ad[br * N_NODES + node];
    float acc[F_IN] = {0, 0, 0, 0, 0, 0, 0, 0, 0};
    float ssum = 0.f;
    for (int k = k0 + lane; k < k1; k += 32) {
        int s = csrc[k];
        float e = as[s] + ad_n;
        e = e > 0.f ? e : 0.2f * e;
        e = fminf(e, 80.f);
        float ex = __expf(e);
        ssum += ex;
        const float* xs = x + s * F_IN;
#pragma unroll
        for (int f = 0; f < F_IN; f++) acc[f] += ex * xs[f];
    }
#pragma unroll
    for (int o = 16; o > 0; o >>= 1) {
        ssum += __shfl_xor_sync(FULL, ssum, o);
#pragma unroll
        for (int f = 0; f < F_IN; f++) acc[f] += __shfl_xor_sync(FULL, acc[f], o);
    }
    float inv = 1.f / ssum;
    int c0 = 2 * lane;
    float y0 = bs[c0], y1 = bs[c0 + 1];
#pragma unroll
    for (int f = 0; f < F_IN; f++) {
        float v = acc[f] * inv;
        y0 += v * Ws[f * U + c0];
        y1 += v * Ws[f * U + c0 + 1];
    }
    __half2* out2 = reinterpret_cast<__half2*>(g_bufA) + ((size_t)br * N_NODES + node) * 32;
    out2[lane] = __floats2half2_rn(tanhf(y0), tanhf(y1));
}

// GEMV helper: in[16-lane group regs v0..v3] @ Wsm[64x64] -> out 4 ch/lane
__device__ __forceinline__ void gemv64(const float4* __restrict__ Wsm,
                                       float v0, float v1, float v2, float v3,
                                       int gbase, int sub,
                                       float& y0, float& y1, float& y2, float& y3) {
#pragma unroll 4
    for (int q = 0; q < 16; q++) {
        int sl = gbase | q;
        float s0 = __shfl_sync(FULL, v0, sl);
        float s1 = __shfl_sync(FULL, v1, sl);
        float s2 = __shfl_sync(FULL, v2, sl);
        float s3 = __shfl_sync(FULL, v3, sl);
        float4 w0 = Wsm[(4 * q + 0) * 16 + sub];
        float4 w1 = Wsm[(4 * q + 1) * 16 + sub];
        float4 w2 = Wsm[(4 * q + 2) * 16 + sub];
        float4 w3 = Wsm[(4 * q + 3) * 16 + sub];
        y0 += s0 * w0.x + s1 * w1.x + s2 * w2.x + s3 * w3.x;
        y1 += s0 * w0.y + s1 * w1.y + s2 * w2.y + s3 * w3.y;
        y2 += s0 * w0.z + s1 * w1.z + s2 * w2.z + s3 * w3.z;
        y3 += s0 * w0.w + s1 * w1.w + s2 * w2.w + s3 * w3.w;
    }
}

// ---------------- GCN layer 1: 2 nodes/warp, bufA -> bufB ----------------
__global__ void __launch_bounds__(256) k_gcn1(const float* __restrict__ W,
                                              const float* __restrict__ b) {
    __shared__ float4 Ws4[U * U / 4];
    __shared__ float4 bs4[U / 4];
    int tid = threadIdx.x;
    for (int i = tid; i < U * U; i += blockDim.x) ((float*)Ws4)[i] = W[i];
    if (tid < U) ((float*)bs4)[tid] = b[tid];
    __syncthreads();
    int br = blockIdx.y;
    int lane = tid & 31, warp = tid >> 5;
    int sub = lane & 15, gbase = lane & 16;
    int node = (blockIdx.x * 8 + warp) * 2 + (lane >> 4);
    bool valid = node < N_NODES;
    const int*   csrc = g_csrc + br * E_TOT;
    const int*   rp   = g_rowptr + br * (N_NODES + 1);
    const float* dinv = g_dinv + br * N_NODES;
    const uint2* x4   = g_bufA + (size_t)br * N_NODES * 16;
    int k0 = 0, k1 = 0;
    if (valid) { k0 = rp[node]; k1 = rp[node + 1]; }
    float dn = valid ? dinv[node] : 0.f;
    int trips = (k1 - k0 + 15) >> 4;
    trips = max(trips, __shfl_xor_sync(FULL, trips, 16));
    float a0 = 0, a1 = 0, a2 = 0, a3 = 0;
    for (int t = 0; t < trips; t++) {
        int k = k0 + t * 16 + sub;
        int s_l = 0; float d_l = 0.f;
        if (k < k1) { s_l = csrc[k]; d_l = dinv[s_l]; }
#pragma unroll
        for (int j = 0; j < 16; j++) {
            int sl = gbase | j;
            int   s  = __shfl_sync(FULL, s_l, sl);
            float cf = __shfl_sync(FULL, d_l, sl) * dn;
            uint2 v = x4[s * 16 + sub];
            float2 f0 = __half22float2(*(__half2*)&v.x);
            float2 f1 = __half22float2(*(__half2*)&v.y);
            a0 += cf * f0.x; a1 += cf * f0.y;
            a2 += cf * f1.x; a3 += cf * f1.y;
        }
    }
    float4 bv = bs4[sub];
    float y0 = bv.x, y1 = bv.y, y2 = bv.z, y3 = bv.w;
    gemv64(Ws4, a0, a1, a2, a3, gbase, sub, y0, y1, y2, y3);
    if (valid) {
        __half2 h0 = __floats2half2_rn(tanhf(y0), tanhf(y1));
        __half2 h1 = __floats2half2_rn(tanhf(y2), tanhf(y3));
        uint2 o;
        o.x = *(unsigned*)&h0; o.y = *(unsigned*)&h1;
        (g_bufB + (size_t)br * N_NODES * 16)[node * 16 + sub] = o;
    }
}

// ---------------- GCN layer 2 + MLP + mean-pool, 2 nodes/warp ----------------
__global__ void __launch_bounds__(256) k_gcn2_mlp(
                           const float* __restrict__ W, const float* __restrict__ b,
                           const int* __restrict__ ba, const int* __restrict__ bb,
                           const float* __restrict__ W1, const float* __restrict__ b1,
                           const float* __restrict__ W2, const float* __restrict__ b2,
                           const float* __restrict__ W3, const float* __restrict__ b3) {
    __shared__ float4 Ws4[U * U / 4], W1s4[U * U / 4];
    __shared__ float2 W2s2[U * 16];
    __shared__ float4 bs4[U / 4], b1s4[U / 4];
    __shared__ float  b2s[32], W3s[32], b3s;
    int tid = threadIdx.x;
    for (int i = tid; i < U * U; i += blockDim.x) {
        ((float*)Ws4)[i] = W[i];
        ((float*)W1s4)[i] = W1[i];
    }
    for (int i = tid; i < U * 32; i += blockDim.x) ((float*)W2s2)[i] = W2[i];
    if (tid < U)  { ((float*)bs4)[tid] = b[tid]; ((float*)b1s4)[tid] = b1[tid]; }
    if (tid < 32) { b2s[tid] = b2[tid]; W3s[tid] = W3[tid]; }
    if (tid == 0) b3s = b3[0];
    __syncthreads();
    int br = blockIdx.y;
    int lane = tid & 31, warp = tid >> 5;
    int sub = lane & 15, gbase = lane & 16;
    int node = (blockIdx.x * 8 + warp) * 2 + (lane >> 4);
    bool valid = node < N_NODES;
    const int*   csrc = g_csrc + br * E_TOT;
    const int*   rp   = g_rowptr + br * (N_NODES + 1);
    const float* dinv = g_dinv + br * N_NODES;
    const uint2* x4   = g_bufB + (size_t)br * N_NODES * 16;
    int k0 = 0, k1 = 0;
    if (valid) { k0 = rp[node]; k1 = rp[node + 1]; }
    float dn = valid ? dinv[node] : 0.f;
    int trips = (k1 - k0 + 15) >> 4;
    trips = max(trips, __shfl_xor_sync(FULL, trips, 16));
    float a0 = 0, a1 = 0, a2 = 0, a3 = 0;
    for (int t = 0; t < trips; t++) {
        int k = k0 + t * 16 + sub;
        int s_l = 0; float d_l = 0.f;
        if (k < k1) { s_l = csrc[k]; d_l = dinv[s_l]; }
#pragma unroll
        for (int j = 0; j < 16; j++) {
            int sl = gbase | j;
            int   s  = __shfl_sync(FULL, s_l, sl);
            float cf = __shfl_sync(FULL, d_l, sl) * dn;
            uint2 v = x4[s * 16 + sub];
            float2 f0 = __half22float2(*(__half2*)&v.x);
            float2 f1 = __half22float2(*(__half2*)&v.y);
            a0 += cf * f0.x; a1 += cf * f0.y;
            a2 += cf * f1.x; a3 += cf * f1.y;
        }
    }
    // GCN GEMV + tanh
    float4 bv = bs4[sub];
    float y0 = bv.x, y1 = bv.y, y2 = bv.z, y3 = bv.w;
    gemv64(Ws4, a0, a1, a2, a3, gbase, sub, y0, y1, y2, y3);
    y0 = tanhf(y0); y1 = tanhf(y1); y2 = tanhf(y2); y3 = tanhf(y3);
    // MLP1 GEMV + tanh
    float4 b1v = b1s4[sub];
    float z0 = b1v.x, z1 = b1v.y, z2 = b1v.z, z3 = b1v.w;
    gemv64(W1s4, y0, y1, y2, y3, gbase, sub, z0, z1, z2, z3);
    z0 = tanhf(z0); z1 = tanhf(z1); z2 = tanhf(z2); z3 = tanhf(z3);
    // MLP2 (64->32): 2 channels per lane (2sub, 2sub+1)
    float p0 = b2s[2 * sub], p1 = b2s[2 * sub + 1];
#pragma unroll 4
    for (int q = 0; q < 16; q++) {
        int sl = gbase | q;
        float v0 = __shfl_sync(FULL, z0, sl);
        float v1 = __shfl_sync(FULL, z1, sl);
        float v2 = __shfl_sync(FULL, z2, sl);
        float v3 = __shfl_sync(FULL, z3, sl);
        float2 w0 = W2s2[(4 * q + 0) * 16 + sub];
        float2 w1 = W2s2[(4 * q + 1) * 16 + sub];
        float2 w2 = W2s2[(4 * q + 2) * 16 + sub];
        float2 w3 = W2s2[(4 * q + 3) * 16 + sub];
        p0 += v0 * w0.x + v1 * w1.x + v2 * w2.x + v3 * w3.x;
        p1 += v0 * w0.y + v1 * w1.y + v2 * w2.y + v3 * w3.y;
    }
    p0 = tanhf(p0); p1 = tanhf(p1);
    // MLP3 (32->1), reduce within 16-lane group
    float c = p0 * W3s[2 * sub] + p1 * W3s[2 * sub + 1];
#pragma unroll
    for (int o = 8; o > 0; o >>= 1) c += __shfl_xor_sync(FULL, c, o);
    if (valid && sub == 0) {
        const int* batch = br ? bb : ba;
        int g = batch[node];
        atomicAdd(&g_psum[br * NG + g], c + b3s);
        atomicAdd(&g_pcnt[br * NG + g], 1.0f);
    }
}

// ---------------- final ----------------
__global__ void k_final(float* __restrict__ out) {
    int g = blockIdx.x * blockDim.x + threadIdx.x;
    if (g >= NG) return;
    float ua = g_psum[g]      / fmaxf(g_pcnt[g], 1.f);
    float ub = g_psum[NG + g] / fmaxf(g_pcnt[NG + g], 1.f);
    out[g] = 1.f / (1.f + expf(-(ub - ua)));
}

// ---------------- host orchestration ----------------
extern "C" void kernel_launch(void* const* d_in, const int* in_sizes, int n_in,
                              void* d_out, int out_size) {
    const float* x_a   = (const float*)d_in[0];
    const float* x_b   = (const float*)d_in[1];
    const int*   ei_a  = (const int*)  d_in[2];
    const int*   ei_b  = (const int*)  d_in[3];
    const int*   ba    = (const int*)  d_in[4];
    const int*   bb    = (const int*)  d_in[5];
    const float* Wgat  = (const float*)d_in[6];
    const float* a_src = (const float*)d_in[7];
    const float* a_dst = (const float*)d_in[8];
    const float* bgat  = (const float*)d_in[9];
    const float* Wgcn  = (const float*)d_in[10];
    const float* bgcn  = (const float*)d_in[11];
    const float* W1    = (const float*)d_in[12];
    const float* b1    = (const float*)d_in[13];
    const float* W2    = (const float*)d_in[14];
    const float* b2    = (const float*)d_in[15];
    const float* W3    = (const float*)d_in[16];
    const float* b3    = (const float*)d_in[17];

    dim3 gE((E_TOT + 255) / 256, 2);
    dim3 gS(SCAN_NB, 2);
    dim3 gN((N_NODES + 255) / 256, 2);
    dim3 gW((N_NODES + 7) / 8, 2);      // 1 node/warp kernels
    dim3 gW2((N_NODES + 15) / 16, 2);   // 2 nodes/warp kernels

    k_pre<<<(2 * N_NODES + 255) / 256, 256>>>(Wgat, a_src, a_dst);
    k_deg<<<gE, 256>>>(ei_a, ei_b);
    k_scan1<<<gS, SCAN_B>>>();
    k_scan3<<<gN, 256>>>(x_a, x_b);
    k_fill<<<gE, 256>>>(ei_a, ei_b);
    k_gat_gather<<<gW, 256>>>(x_a, x_b, Wgat, bgat);
    k_gcn1<<<gW2, 256>>>(Wgcn, bgcn);
    k_gcn2_mlp<<<gW2, 256>>>(Wgcn + U * U, bgcn + U, ba, bb,
                             W1, b1, W2, b2, W3, b3);
    k_final<<<2, 256>>>((float*)d_out);
}

// round 10
// speedup vs baseline: 1.6914x; 1.0053x over previous
#include <cuda_runtime.h>
#include <cuda_fp16.h>
#include <math.h>

#define N_NODES 50000
#define N_EDGES 800000
#define E_TOT   850000   // edges + self loops
#define U       64
#define NG      512
#define F_IN    9
#define SCAN_B  1024
#define SCAN_NB ((N_NODES + SCAN_B - 1) / SCAN_B)   // 49
#define FULL    0xffffffffu

// ---------------- scratch (device globals; no allocations) ----------------
__device__ uint2  g_bufA[2 * N_NODES * 16];   // fp16 features, 64 half per node
__device__ uint2  g_bufB[2 * N_NODES * 16];
__device__ float4 g_xpack[2 * N_NODES * 3];   // [as, x0..x8, pad, pad] per node
__device__ float  g_ad[2 * N_NODES];
__device__ float  g_dinv[2 * N_NODES];
__device__ int    g_deg[2 * N_NODES];
__device__ int    g_rowtmp[2 * N_NODES];
__device__ int    g_rowptr[2 * (N_NODES + 1)];
__device__ int    g_cursor[2 * N_NODES];
__device__ int    g_bsum[2 * SCAN_NB];
__device__ int    g_csrc[2 * E_TOT];
__device__ float  g_wa[F_IN], g_wd[F_IN];
__device__ float  g_psum[2 * NG];
__device__ float  g_pcnt[2 * NG];

__device__ __forceinline__ void edge_src_dst(int e, const int* __restrict__ ei,
                                             int& src, int& dst) {
    if (e < N_EDGES) { src = ei[e]; dst = ei[N_EDGES + e]; }
    else             { src = e - N_EDGES; dst = src; }
}

// ---------------- pre: zero deg + pool, compute wa/wd ----------------
__global__ void k_pre(const float* __restrict__ W, const float* __restrict__ a_src,
                      const float* __restrict__ a_dst) {
    int i = blockIdx.x * blockDim.x + threadIdx.x;
    if (i < 2 * N_NODES) g_deg[i] = 0;
    if (i < 2 * NG) { g_psum[i] = 0.f; g_pcnt[i] = 0.f; }
    if (blockIdx.x == 0) {
        int t = threadIdx.x;
        if (t < F_IN) {
            float s = 0.f;
            for (int c = 0; c < U; c++) s += W[t * U + c] * a_src[c];
            g_wa[t] = s;
        } else if (t >= 16 && t < 16 + F_IN) {
            int f = t - 16;
            float s = 0.f;
            for (int c = 0; c < U; c++) s += W[f * U + c] * a_dst[c];
            g_wd[f] = s;
        }
    }
}

// ---------------- CSR build ----------------
__global__ void k_deg(const int* __restrict__ ei_a, const int* __restrict__ ei_b) {
    int br = blockIdx.y;
    int e = blockIdx.x * blockDim.x + threadIdx.x;
    if (e >= E_TOT) return;
    const int* ei = br ? ei_b : ei_a;
    int src, dst; edge_src_dst(e, ei, src, dst);
    atomicAdd(&g_deg[br * N_NODES + dst], 1);
}
__global__ void k_scan1() {
    __shared__ int sm[SCAN_B];
    int br = blockIdx.y;
    int t = threadIdx.x;
    int i = blockIdx.x * SCAN_B + t;
    int v = (i < N_NODES) ? g_deg[br * N_NODES + i] : 0;
    sm[t] = v;
    __syncthreads();
#pragma unroll
    for (int off = 1; off < SCAN_B; off <<= 1) {
        int add = (t >= off) ? sm[t - off] : 0;
        __syncthreads();
        sm[t] += add;
        __syncthreads();
    }
    if (i < N_NODES) g_rowtmp[br * N_NODES + i] = sm[t];
    if (t == SCAN_B - 1) g_bsum[br * SCAN_NB + blockIdx.x] = sm[t];
}
// scan3: finalize CSR + write packed [as, x0..x8] record per node
__global__ void k_scan3(const float* __restrict__ xa, const float* __restrict__ xb) {
    __shared__ int bsm[SCAN_NB];
    int br = blockIdx.y;
    int t = threadIdx.x;
    if (t < SCAN_NB) bsm[t] = g_bsum[br * SCAN_NB + t];
    __syncthreads();
    int i = blockIdx.x * blockDim.x + t;
    if (i >= N_NODES) return;
    int blk = i / SCAN_B;
    int pre = 0;
    for (int b = 0; b < blk; b++) pre += bsm[b];
    int incl = g_rowtmp[br * N_NODES + i] + pre;
    int d = g_deg[br * N_NODES + i];
    g_rowptr[br * (N_NODES + 1) + i + 1] = incl;
    g_cursor[br * N_NODES + i] = incl - d;
    g_dinv[br * N_NODES + i] = rsqrtf((float)d);
    if (i == 0) g_rowptr[br * (N_NODES + 1)] = 0;
    const float* x = br ? xb : xa;
    const float* xi = x + i * F_IN;
    float v[F_IN];
    float as = 0.f, ad = 0.f;
#pragma unroll
    for (int f = 0; f < F_IN; f++) {
        v[f] = xi[f];
        as += v[f] * g_wa[f];
        ad += v[f] * g_wd[f];
    }
    g_ad[br * N_NODES + i] = ad;
    float4* xp = g_xpack + ((size_t)br * N_NODES + i) * 3;
    xp[0] = make_float4(as, v[0], v[1], v[2]);
    xp[1] = make_float4(v[3], v[4], v[5], v[6]);
    xp[2] = make_float4(v[7], v[8], 0.f, 0.f);
}
__global__ void k_fill(const int* __restrict__ ei_a, const int* __restrict__ ei_b) {
    int br = blockIdx.y;
    int e = blockIdx.x * blockDim.x + threadIdx.x;
    if (e >= E_TOT) return;
    const int* ei = br ? ei_b : ei_a;
    int src, dst; edge_src_dst(e, ei, src, dst);
    int pos = atomicAdd(&g_cursor[br * N_NODES + dst], 1);
    g_csrc[br * E_TOT + pos] = src;
}

// ---------------- GAT: softmax-weighted aggregate of packed x, then @W ------
__global__ void k_gat_gather(const float* __restrict__ W, const float* __restrict__ b) {
    __shared__ float Ws[F_IN * U];
    __shared__ float bs[U];
    int tid = threadIdx.x;
    for (int i = tid; i < F_IN * U; i += blockDim.x) Ws[i] = W[i];
    if (tid < U) bs[tid] = b[tid];
    __syncthreads();
    int br = blockIdx.y;
    int lane = tid & 31;
    int node = blockIdx.x * (blockDim.x >> 5) + (tid >> 5);
    if (node >= N_NODES) return;
    const int*    csrc = g_csrc + br * E_TOT;
    const int*    rp   = g_rowptr + br * (N_NODES + 1);
    const float4* xp   = g_xpack + (size_t)br * N_NODES * 3;
    int k0 = rp[node], k1 = rp[node + 1];
    float ad_n = g_ad[br * N_NODES + node];
    float acc[F_IN] = {0, 0, 0, 0, 0, 0, 0, 0, 0};
    float ssum = 0.f;
    for (int k = k0 + lane; k < k1; k += 32) {
        int s = csrc[k];
        float4 p0 = xp[s * 3 + 0];
        float4 p1 = xp[s * 3 + 1];
        float4 p2 = xp[s * 3 + 2];
        float e = p0.x + ad_n;           // p0.x = as[s]
        e = e > 0.f ? e : 0.2f * e;
        e = fminf(e, 80.f);
        float ex = __expf(e);
        ssum += ex;
        acc[0] += ex * p0.y; acc[1] += ex * p0.z; acc[2] += ex * p0.w;
        acc[3] += ex * p1.x; acc[4] += ex * p1.y; acc[5] += ex * p1.z;
        acc[6] += ex * p1.w; acc[7] += ex * p2.x; acc[8] += ex * p2.y;
    }
#pragma unroll
    for (int o = 16; o > 0; o >>= 1) {
        ssum += __shfl_xor_sync(FULL, ssum, o);
#pragma unroll
        for (int f = 0; f < F_IN; f++) acc[f] += __shfl_xor_sync(FULL, acc[f], o);
    }
    float inv = 1.f / ssum;
    int c0 = 2 * lane;
    float y0 = bs[c0], y1 = bs[c0 + 1];
#pragma unroll
    for (int f = 0; f < F_IN; f++) {
        float v = acc[f] * inv;
        y0 += v * Ws[f * U + c0];
        y1 += v * Ws[f * U + c0 + 1];
    }
    __half2* out2 = reinterpret_cast<__half2*>(g_bufA) + ((size_t)br * N_NODES + node) * 32;
    out2[lane] = __floats2half2_rn(tanhf(y0), tanhf(y1));
}

// GEMV helper: in[16-lane group regs v0..v3] @ Wsm[64x64] -> out 4 ch/lane
__device__ __forceinline__ void gemv64(const float4* __restrict__ Wsm,
                                       float v0, float v1, float v2, float v3,
                                       int gbase, int sub,
                                       float& y0, float& y1, float& y2, float& y3) {
#pragma unroll 4
    for (int q = 0; q < 16; q++) {
        int sl = gbase | q;
        float s0 = __shfl_sync(FULL, v0, sl);
        float s1 = __shfl_sync(FULL, v1, sl);
        float s2 = __shfl_sync(FULL, v2, sl);
        float s3 = __shfl_sync(FULL, v3, sl);
        float4 w0 = Wsm[(4 * q + 0) * 16 + sub];
        float4 w1 = Wsm[(4 * q + 1) * 16 + sub];
        float4 w2 = Wsm[(4 * q + 2) * 16 + sub];
        float4 w3 = Wsm[(4 * q + 3) * 16 + sub];
        y0 += s0 * w0.x + s1 * w1.x + s2 * w2.x + s3 * w3.x;
        y1 += s0 * w0.y + s1 * w1.y + s2 * w2.y + s3 * w3.y;
        y2 += s0 * w0.z + s1 * w1.z + s2 * w2.z + s3 * w3.z;
        y3 += s0 * w0.w + s1 * w1.w + s2 * w2.w + s3 * w3.w;
    }
}

// ---------------- GCN layer 1: 2 nodes/warp, bufA -> bufB ----------------
__global__ void __launch_bounds__(256) k_gcn1(const float* __restrict__ W,
                                              const float* __restrict__ b) {
    __shared__ float4 Ws4[U * U / 4];
    __shared__ float4 bs4[U / 4];
    int tid = threadIdx.x;
    for (int i = tid; i < U * U; i += blockDim.x) ((float*)Ws4)[i] = W[i];
    if (tid < U) ((float*)bs4)[tid] = b[tid];
    __syncthreads();
    int br = blockIdx.y;
    int lane = tid & 31, warp = tid >> 5;
    int sub = lane & 15, gbase = lane & 16;
    int node = (blockIdx.x * 8 + warp) * 2 + (lane >> 4);
    bool valid = node < N_NODES;
    const int*   csrc = g_csrc + br * E_TOT;
    const int*   rp   = g_rowptr + br * (N_NODES + 1);
    const float* dinv = g_dinv + br * N_NODES;
    const uint2* x4   = g_bufA + (size_t)br * N_NODES * 16;
    int k0 = 0, k1 = 0;
    if (valid) { k0 = rp[node]; k1 = rp[node + 1]; }
    float dn = valid ? dinv[node] : 0.f;
    int trips = (k1 - k0 + 15) >> 4;
    trips = max(trips, __shfl_xor_sync(FULL, trips, 16));
    float a0 = 0, a1 = 0, a2 = 0, a3 = 0;
    for (int t = 0; t < trips; t++) {
        int k = k0 + t * 16 + sub;
        int s_l = 0; float d_l = 0.f;
        if (k < k1) { s_l = csrc[k]; d_l = dinv[s_l]; }
#pragma unroll
        for (int j = 0; j < 16; j++) {
            int sl = gbase | j;
            int   s  = __shfl_sync(FULL, s_l, sl);
            float cf = __shfl_sync(FULL, d_l, sl) * dn;
            uint2 v = x4[s * 16 + sub];
            float2 f0 = __half22float2(*(__half2*)&v.x);
            float2 f1 = __half22float2(*(__half2*)&v.y);
            a0 += cf * f0.x; a1 += cf * f0.y;
            a2 += cf * f1.x; a3 += cf * f1.y;
        }
    }
    float4 bv = bs4[sub];
    float y0 = bv.x, y1 = bv.y, y2 = bv.z, y3 = bv.w;
    gemv64(Ws4, a0, a1, a2, a3, gbase, sub, y0, y1, y2, y3);
    if (valid) {
        __half2 h0 = __floats2half2_rn(tanhf(y0), tanhf(y1));
        __half2 h1 = __floats2half2_rn(tanhf(y2), tanhf(y3));
        uint2 o;
        o.x = *(unsigned*)&h0; o.y = *(unsigned*)&h1;
        (g_bufB + (size_t)br * N_NODES * 16)[node * 16 + sub] = o;
    }
}

// ---------------- GCN layer 2 + MLP + mean-pool, 2 nodes/warp ----------------
__global__ void __launch_bounds__(256) k_gcn2_mlp(
                           const float* __restrict__ W, const float* __restrict__ b,
                           const int* __restrict__ ba, const int* __restrict__ bb,
                           const float* __restrict__ W1, const float* __restrict__ b1,
                           const float* __restrict__ W2, const float* __restrict__ b2,
                           const float* __restrict__ W3, const float* __restrict__ b3) {
    __shared__ float4 Ws4[U * U / 4], W1s4[U * U / 4];
    __shared__ float2 W2s2[U * 16];
    __shared__ float4 bs4[U / 4], b1s4[U / 4];
    __shared__ float  b2s[32], W3s[32], b3s;
    int tid = threadIdx.x;
    for (int i = tid; i < U * U; i += blockDim.x) {
        ((float*)Ws4)[i] = W[i];
        ((float*)W1s4)[i] = W1[i];
    }
    for (int i = tid; i < U * 32; i += blockDim.x) ((float*)W2s2)[i] = W2[i];
    if (tid < U)  { ((float*)bs4)[tid] = b[tid]; ((float*)b1s4)[tid] = b1[tid]; }
    if (tid < 32) { b2s[tid] = b2[tid]; W3s[tid] = W3[tid]; }
    if (tid == 0) b3s = b3[0];
    __syncthreads();
    int br = blockIdx.y;
    int lane = tid & 31, warp = tid >> 5;
    int sub = lane & 15, gbase = lane & 16;
    int node = (blockIdx.x * 8 + warp) * 2 + (lane >> 4);
    bool valid = node < N_NODES;
    const int*   csrc = g_csrc + br * E_TOT;
    const int*   rp   = g_rowptr + br * (N_NODES + 1);
    const float* dinv = g_dinv + br * N_NODES;
    const uint2* x4   = g_bufB + (size_t)br * N_NODES * 16;
    int k0 = 0, k1 = 0;
    if (valid) { k0 = rp[node]; k1 = rp[node + 1]; }
    float dn = valid ? dinv[node] : 0.f;
    int trips = (k1 - k0 + 15) >> 4;
    trips = max(trips, __shfl_xor_sync(FULL, trips, 16));
    float a0 = 0, a1 = 0, a2 = 0, a3 = 0;
    for (int t = 0; t < trips; t++) {
        int k = k0 + t * 16 + sub;
        int s_l = 0; float d_l = 0.f;
        if (k < k1) { s_l = csrc[k]; d_l = dinv[s_l]; }
#pragma unroll
        for (int j = 0; j < 16; j++) {
            int sl = gbase | j;
            int   s  = __shfl_sync(FULL, s_l, sl);
            float cf = __shfl_sync(FULL, d_l, sl) * dn;
            uint2 v = x4[s * 16 + sub];
            float2 f0 = __half22float2(*(__half2*)&v.x);
            float2 f1 = __half22float2(*(__half2*)&v.y);
            a0 += cf * f0.x; a1 += cf * f0.y;
            a2 += cf * f1.x; a3 += cf * f1.y;
        }
    }
    // GCN GEMV + tanh
    float4 bv = bs4[sub];
    float y0 = bv.x, y1 = bv.y, y2 = bv.z, y3 = bv.w;
    gemv64(Ws4, a0, a1, a2, a3, gbase, sub, y0, y1, y2, y3);
    y0 = tanhf(y0); y1 = tanhf(y1); y2 = tanhf(y2); y3 = tanhf(y3);
    // MLP1 GEMV + tanh
    float4 b1v = b1s4[sub];
    float z0 = b1v.x, z1 = b1v.y, z2 = b1v.z, z3 = b1v.w;
    gemv64(W1s4, y0, y1, y2, y3, gbase, sub, z0, z1, z2, z3);
    z0 = tanhf(z0); z1 = tanhf(z1); z2 = tanhf(z2); z3 = tanhf(z3);
    // MLP2 (64->32): 2 channels per lane (2sub, 2sub+1)
    float p0 = b2s[2 * sub], p1 = b2s[2 * sub + 1];
#pragma unroll 4
    for (int q = 0; q < 16; q++) {
        int sl = gbase | q;
        float v0 = __shfl_sync(FULL, z0, sl);
        float v1 = __shfl_sync(FULL, z1, sl);
        float v2 = __shfl_sync(FULL, z2, sl);
        float v3 = __shfl_sync(FULL, z3, sl);
        float2 w0 = W2s2[(4 * q + 0) * 16 + sub];
        float2 w1 = W2s2[(4 * q + 1) * 16 + sub];
        float2 w2 = W2s2[(4 * q + 2) * 16 + sub];
        float2 w3 = W2s2[(4 * q + 3) * 16 + sub];
        p0 += v0 * w0.x + v1 * w1.x + v2 * w2.x + v3 * w3.x;
        p1 += v0 * w0.y + v1 * w1.y + v2 * w2.y + v3 * w3.y;
    }
    p0 = tanhf(p0); p1 = tanhf(p1);
    // MLP3 (32->1), reduce within 16-lane group
    float c = p0 * W3s[2 * sub] + p1 * W3s[2 * sub + 1];
#pragma unroll
    for (int o = 8; o > 0; o >>= 1) c += __shfl_xor_sync(FULL, c, o);
    if (valid && sub == 0) {
        const int* batch = br ? bb : ba;
        int g = batch[node];
        atomicAdd(&g_psum[br * NG + g], c + b3s);
        atomicAdd(&g_pcnt[br * NG + g], 1.0f);
    }
}

// ---------------- final ----------------
__global__ void k_final(float* __restrict__ out) {
    int g = blockIdx.x * blockDim.x + threadIdx.x;
    if (g >= NG) return;
    float ua = g_psum[g]      / fmaxf(g_pcnt[g], 1.f);
    float ub = g_psum[NG + g] / fmaxf(g_pcnt[NG + g], 1.f);
    out[g] = 1.f / (1.f + expf(-(ub - ua)));
}

// ---------------- host orchestration ----------------
extern "C" void kernel_launch(void* const* d_in, const int* in_sizes, int n_in,
                              void* d_out, int out_size) {
    const float* x_a   = (const float*)d_in[0];
    const float* x_b   = (const float*)d_in[1];
    const int*   ei_a  = (const int*)  d_in[2];
    const int*   ei_b  = (const int*)  d_in[3];
    const int*   ba    = (const int*)  d_in[4];
    const int*   bb    = (const int*)  d_in[5];
    const float* Wgat  = (const float*)d_in[6];
    const float* a_src = (const float*)d_in[7];
    const float* a_dst = (const float*)d_in[8];
    const float* bgat  = (const float*)d_in[9];
    const float* Wgcn  = (const float*)d_in[10];
    const float* bgcn  = (const float*)d_in[11];
    const float* W1    = (const float*)d_in[12];
    const float* b1    = (const float*)d_in[13];
    const float* W2    = (const float*)d_in[14];
    const float* b2    = (const float*)d_in[15];
    const float* W3    = (const float*)d_in[16];
    const float* b3    = (const float*)d_in[17];

    dim3 gE((E_TOT + 255) / 256, 2);
    dim3 gS(SCAN_NB, 2);
    dim3 gN((N_NODES + 255) / 256, 2);
    dim3 gW((N_NODES + 7) / 8, 2);      // 1 node/warp kernels
    dim3 gW2((N_NODES + 15) / 16, 2);   // 2 nodes/warp kernels

    k_pre<<<(2 * N_NODES + 255) / 256, 256>>>(Wgat, a_src, a_dst);
    k_deg<<<gE, 256>>>(ei_a, ei_b);
    k_scan1<<<gS, SCAN_B>>>();
    k_scan3<<<gN, 256>>>(x_a, x_b);
    k_fill<<<gE, 256>>>(ei_a, ei_b);
    k_gat_gather<<<gW, 256>>>(Wgat, bgat);
    k_gcn1<<<gW2, 256>>>(Wgcn, bgcn);
    k_gcn2_mlp<<<gW2, 256>>>(Wgcn + U * U, bgcn + U, ba, bb,
                             W1, b1, W2, b2, W3, b3);
    k_final<<<2, 256>>>((float*)d_out);
}

// round 11
// speedup vs baseline: 1.7313x; 1.0236x over previous
#include <cuda_runtime.h>
#include <cuda_fp16.h>
#include <math.h>

#define N_NODES 50000
#define N_EDGES 800000
#define E_TOT   850000   // edges + self loops
#define U       64
#define NG      512
#define F_IN    9
#define SCAN_B  1024
#define SCAN_NB ((N_NODES + SCAN_B - 1) / SCAN_B)   // 49
#define NTILES  ((N_NODES + 15) / 16)               // 3125 (16 nodes per block-tile)
#define FULL    0xffffffffu

// ---------------- scratch (device globals; no allocations) ----------------
__device__ uint2  g_bufA[2 * N_NODES * 16];   // fp16 features, 64 half per node
__device__ uint2  g_bufB[2 * N_NODES * 16];
__device__ float4 g_xpack[2 * N_NODES * 3];   // [as, x0..x8, pad, pad] per node
__device__ float  g_ad[2 * N_NODES];
__device__ float  g_dinv[2 * N_NODES];
__device__ int    g_deg[2 * N_NODES];
__device__ int    g_rowtmp[2 * N_NODES];
__device__ int    g_rowptr[2 * (N_NODES + 1)];
__device__ int    g_cursor[2 * N_NODES];
__device__ int    g_bsum[2 * SCAN_NB];
__device__ int2   g_ec[2 * E_TOT];            // (src, gcn coef) per CSR slot
__device__ float  g_wa[F_IN], g_wd[F_IN];
__device__ float  g_psum[2 * NG];
__device__ float  g_pcnt[2 * NG];

__device__ __forceinline__ void edge_src_dst(int e, const int* __restrict__ ei,
                                             int& src, int& dst) {
    if (e < N_EDGES) { src = ei[e]; dst = ei[N_EDGES + e]; }
    else             { src = e - N_EDGES; dst = src; }
}

// ---------------- pre: zero deg + pool, compute wa/wd ----------------
__global__ void k_pre(const float* __restrict__ W, const float* __restrict__ a_src,
                      const float* __restrict__ a_dst) {
    int i = blockIdx.x * blockDim.x + threadIdx.x;
    if (i < 2 * N_NODES) g_deg[i] = 0;
    if (i < 2 * NG) { g_psum[i] = 0.f; g_pcnt[i] = 0.f; }
    if (blockIdx.x == 0) {
        int t = threadIdx.x;
        if (t < F_IN) {
            float s = 0.f;
            for (int c = 0; c < U; c++) s += W[t * U + c] * a_src[c];
            g_wa[t] = s;
        } else if (t >= 16 && t < 16 + F_IN) {
            int f = t - 16;
            float s = 0.f;
            for (int c = 0; c < U; c++) s += W[f * U + c] * a_dst[c];
            g_wd[f] = s;
        }
    }
}

// ---------------- CSR build ----------------
__global__ void k_deg(const int* __restrict__ ei_a, const int* __restrict__ ei_b) {
    int br = blockIdx.y;
    int e = blockIdx.x * blockDim.x + threadIdx.x;
    if (e >= E_TOT) return;
    const int* ei = br ? ei_b : ei_a;
    int dst = (e < N_EDGES) ? ei[N_EDGES + e] : (e - N_EDGES);
    atomicAdd(&g_deg[br * N_NODES + dst], 1);
}
__global__ void k_scan1() {
    __shared__ int sm[SCAN_B];
    int br = blockIdx.y;
    int t = threadIdx.x;
    int i = blockIdx.x * SCAN_B + t;
    int v = (i < N_NODES) ? g_deg[br * N_NODES + i] : 0;
    sm[t] = v;
    __syncthreads();
#pragma unroll
    for (int off = 1; off < SCAN_B; off <<= 1) {
        int add = (t >= off) ? sm[t - off] : 0;
        __syncthreads();
        sm[t] += add;
        __syncthreads();
    }
    if (i < N_NODES) g_rowtmp[br * N_NODES + i] = sm[t];
    if (t == SCAN_B - 1) g_bsum[br * SCAN_NB + blockIdx.x] = sm[t];
}
// scan3: finalize CSR + dinv + packed [as, x0..x8] record per node
__global__ void k_scan3(const float* __restrict__ xa, const float* __restrict__ xb) {
    __shared__ int bsm[SCAN_NB];
    int br = blockIdx.y;
    int t = threadIdx.x;
    if (t < SCAN_NB) bsm[t] = g_bsum[br * SCAN_NB + t];
    __syncthreads();
    int i = blockIdx.x * blockDim.x + t;
    if (i >= N_NODES) return;
    int blk = i / SCAN_B;
    int pre = 0;
    for (int b = 0; b < blk; b++) pre += bsm[b];
    int incl = g_rowtmp[br * N_NODES + i] + pre;
    int d = g_deg[br * N_NODES + i];
    g_rowptr[br * (N_NODES + 1) + i + 1] = incl;
    g_cursor[br * N_NODES + i] = incl - d;
    g_dinv[br * N_NODES + i] = rsqrtf((float)d);
    if (i == 0) g_rowptr[br * (N_NODES + 1)] = 0;
    const float* x = br ? xb : xa;
    const float* xi = x + i * F_IN;
    float v[F_IN];
    float as = 0.f, ad = 0.f;
#pragma unroll
    for (int f = 0; f < F_IN; f++) {
        v[f] = xi[f];
        as += v[f] * g_wa[f];
        ad += v[f] * g_wd[f];
    }
    g_ad[br * N_NODES + i] = ad;
    float4* xp = g_xpack + ((size_t)br * N_NODES + i) * 3;
    xp[0] = make_float4(as, v[0], v[1], v[2]);
    xp[1] = make_float4(v[3], v[4], v[5], v[6]);
    xp[2] = make_float4(v[7], v[8], 0.f, 0.f);
}
// fill: CSR slot gets (src, precomputed GCN coefficient)
__global__ void k_fill(const int* __restrict__ ei_a, const int* __restrict__ ei_b) {
    int br = blockIdx.y;
    int e = blockIdx.x * blockDim.x + threadIdx.x;
    if (e >= E_TOT) return;
    const int* ei = br ? ei_b : ei_a;
    int src, dst; edge_src_dst(e, ei, src, dst);
    int pos = atomicAdd(&g_cursor[br * N_NODES + dst], 1);
    float coef = g_dinv[br * N_NODES + src] * g_dinv[br * N_NODES + dst];
    g_ec[br * E_TOT + pos] = make_int2(src, __float_as_int(coef));
}

// ---------------- GAT: softmax-weighted aggregate of packed x, then @W ------
__global__ void k_gat_gather(const float* __restrict__ W, const float* __restrict__ b) {
    __shared__ float Ws[F_IN * U];
    __shared__ float bs[U];
    int tid = threadIdx.x;
    for (int i = tid; i < F_IN * U; i += blockDim.x) Ws[i] = W[i];
    if (tid < U) bs[tid] = b[tid];
    __syncthreads();
    int br = blockIdx.y;
    int lane = tid & 31;
    int node = blockIdx.x * (blockDim.x >> 5) + (tid >> 5);
    if (node >= N_NODES) return;
    const int2*   ec = g_ec + br * E_TOT;
    const int*    rp = g_rowptr + br * (N_NODES + 1);
    const float4* xp = g_xpack + (size_t)br * N_NODES * 3;
    int k0 = rp[node], k1 = rp[node + 1];
    float ad_n = g_ad[br * N_NODES + node];
    float acc[F_IN] = {0, 0, 0, 0, 0, 0, 0, 0, 0};
    float ssum = 0.f;
    for (int k = k0 + lane; k < k1; k += 32) {
        int s = ec[k].x;
        float4 p0 = xp[s * 3 + 0];
        float4 p1 = xp[s * 3 + 1];
        float4 p2 = xp[s * 3 + 2];
        float e = p0.x + ad_n;           // p0.x = as[s]
        e = e > 0.f ? e : 0.2f * e;
        e = fminf(e, 80.f);
        float ex = __expf(e);
        ssum += ex;
        acc[0] += ex * p0.y; acc[1] += ex * p0.z; acc[2] += ex * p0.w;
        acc[3] += ex * p1.x; acc[4] += ex * p1.y; acc[5] += ex * p1.z;
        acc[6] += ex * p1.w; acc[7] += ex * p2.x; acc[8] += ex * p2.y;
    }
#pragma unroll
    for (int o = 16; o > 0; o >>= 1) {
        ssum += __shfl_xor_sync(FULL, ssum, o);
#pragma unroll
        for (int f = 0; f < F_IN; f++) acc[f] += __shfl_xor_sync(FULL, acc[f], o);
    }
    float inv = 1.f / ssum;
    int c0 = 2 * lane;
    float y0 = bs[c0], y1 = bs[c0 + 1];
#pragma unroll
    for (int f = 0; f < F_IN; f++) {
        float v = acc[f] * inv;
        y0 += v * Ws[f * U + c0];
        y1 += v * Ws[f * U + c0 + 1];
    }
    __half2* out2 = reinterpret_cast<__half2*>(g_bufA) + ((size_t)br * N_NODES + node) * 32;
    out2[lane] = __floats2half2_rn(tanhf(y0), tanhf(y1));
}

// GEMV helper: in[16-lane group regs v0..v3] @ Wsm[64x64] -> out 4 ch/lane
__device__ __forceinline__ void gemv64(const float4* __restrict__ Wsm,
                                       float v0, float v1, float v2, float v3,
                                       int gbase, int sub,
                                       float& y0, float& y1, float& y2, float& y3) {
#pragma unroll 4
    for (int q = 0; q < 16; q++) {
        int sl = gbase | q;
        float s0 = __shfl_sync(FULL, v0, sl);
        float s1 = __shfl_sync(FULL, v1, sl);
        float s2 = __shfl_sync(FULL, v2, sl);
        float s3 = __shfl_sync(FULL, v3, sl);
        float4 w0 = Wsm[(4 * q + 0) * 16 + sub];
        float4 w1 = Wsm[(4 * q + 1) * 16 + sub];
        float4 w2 = Wsm[(4 * q + 2) * 16 + sub];
        float4 w3 = Wsm[(4 * q + 3) * 16 + sub];
        y0 += s0 * w0.x + s1 * w1.x + s2 * w2.x + s3 * w3.x;
        y1 += s0 * w0.y + s1 * w1.y + s2 * w2.y + s3 * w3.y;
        y2 += s0 * w0.z + s1 * w1.z + s2 * w2.z + s3 * w3.z;
        y3 += s0 * w0.w + s1 * w1.w + s2 * w2.w + s3 * w3.w;
    }
}

// gather core for one node pair: returns 4-channel accumulators
__device__ __forceinline__ void gcn_edge_gather(const int2* __restrict__ ec,
                                                const int* __restrict__ rp,
                                                const uint2* __restrict__ x4,
                                                int node, bool valid,
                                                int gbase, int sub,
                                                float& a0, float& a1, float& a2, float& a3) {
    int k0 = 0, k1 = 0;
    if (valid) { k0 = rp[node]; k1 = rp[node + 1]; }
    int trips = (k1 - k0 + 15) >> 4;
    trips = max(trips, __shfl_xor_sync(FULL, trips, 16));
    a0 = 0.f; a1 = 0.f; a2 = 0.f; a3 = 0.f;
    for (int t = 0; t < trips; t++) {
        int k = k0 + t * 16 + sub;
        int2 e_l = make_int2(0, 0);      // coef 0 -> padding contributes nothing
        if (k < k1) e_l = ec[k];
#pragma unroll
        for (int j = 0; j < 16; j++) {
            int sl = gbase | j;
            int   s  = __shfl_sync(FULL, e_l.x, sl);
            float cf = __uint_as_float(__shfl_sync(FULL, e_l.y, sl));
            uint2 v = x4[s * 16 + sub];
            float2 f0 = __half22float2(*(__half2*)&v.x);
            float2 f1 = __half22float2(*(__half2*)&v.y);
            a0 += cf * f0.x; a1 += cf * f0.y;
            a2 += cf * f1.x; a3 += cf * f1.y;
        }
    }
}

// ---------------- GCN layer 1: persistent, 2 nodes/warp, bufA -> bufB --------
__global__ void __launch_bounds__(256) k_gcn1(const float* __restrict__ W,
                                              const float* __restrict__ b) {
    __shared__ float4 Ws4[U * U / 4];
    __shared__ float4 bs4[U / 4];
    int tid = threadIdx.x;
    for (int i = tid; i < U * U; i += blockDim.x) ((float*)Ws4)[i] = W[i];
    if (tid < U) ((float*)bs4)[tid] = b[tid];
    __syncthreads();
    int br = blockIdx.y;
    int lane = tid & 31, warp = tid >> 5;
    int sub = lane & 15, gbase = lane & 16;
    const int2*  ec = g_ec + br * E_TOT;
    const int*   rp = g_rowptr + br * (N_NODES + 1);
    const uint2* x4 = g_bufA + (size_t)br * N_NODES * 16;
    uint2* outb = g_bufB + (size_t)br * N_NODES * 16;
    for (int tile = blockIdx.x; tile < NTILES; tile += gridDim.x) {
        int node = (tile * 8 + warp) * 2 + (lane >> 4);
        bool valid = node < N_NODES;
        float a0, a1, a2, a3;
        gcn_edge_gather(ec, rp, x4, node, valid, gbase, sub, a0, a1, a2, a3);
        float4 bv = bs4[sub];
        float y0 = bv.x, y1 = bv.y, y2 = bv.z, y3 = bv.w;
        gemv64(Ws4, a0, a1, a2, a3, gbase, sub, y0, y1, y2, y3);
        if (valid) {
            __half2 h0 = __floats2half2_rn(tanhf(y0), tanhf(y1));
            __half2 h1 = __floats2half2_rn(tanhf(y2), tanhf(y3));
            uint2 o;
            o.x = *(unsigned*)&h0; o.y = *(unsigned*)&h1;
            outb[node * 16 + sub] = o;
        }
    }
}

// ---------------- GCN layer 2 + MLP + mean-pool, persistent, 2 nodes/warp ----
__global__ void __launch_bounds__(256) k_gcn2_mlp(
                           const float* __restrict__ W, const float* __restrict__ b,
                           const int* __restrict__ ba, const int* __restrict__ bb,
                           const float* __restrict__ W1, const float* __restrict__ b1,
                           const float* __restrict__ W2, const float* __restrict__ b2,
                           const float* __restrict__ W3, const float* __restrict__ b3) {
    __shared__ float4 Ws4[U * U / 4], W1s4[U * U / 4];
    __shared__ float2 W2s2[U * 16];
    __shared__ float4 bs4[U / 4], b1s4[U / 4];
    __shared__ float  b2s[32], W3s[32], b3s;
    int tid = threadIdx.x;
    for (int i = tid; i < U * U; i += blockDim.x) {
        ((float*)Ws4)[i] = W[i];
        ((float*)W1s4)[i] = W1[i];
    }
    for (int i = tid; i < U * 32; i += blockDim.x) ((float*)W2s2)[i] = W2[i];
    if (tid < U)  { ((float*)bs4)[tid] = b[tid]; ((float*)b1s4)[tid] = b1[tid]; }
    if (tid < 32) { b2s[tid] = b2[tid]; W3s[tid] = W3[tid]; }
    if (tid == 0) b3s = b3[0];
    __syncthreads();
    int br = blockIdx.y;
    int lane = tid & 31, warp = tid >> 5;
    int sub = lane & 15, gbase = lane & 16;
    const int2*  ec = g_ec + br * E_TOT;
    const int*   rp = g_rowptr + br * (N_NODES + 1);
    const uint2* x4 = g_bufB + (size_t)br * N_NODES * 16;
    const int* batch = br ? bb : ba;
    for (int tile = blockIdx.x; tile < NTILES; tile += gridDim.x) {
        int node = (tile * 8 + warp) * 2 + (lane >> 4);
        bool valid = node < N_NODES;
        float a0, a1, a2, a3;
        gcn_edge_gather(ec, rp, x4, node, valid, gbase, sub, a0, a1, a2, a3);
        // GCN GEMV + tanh
        float4 bv = bs4[sub];
        float y0 = bv.x, y1 = bv.y, y2 = bv.z, y3 = bv.w;
        gemv64(Ws4, a0, a1, a2, a3, gbase, sub, y0, y1, y2, y3);
        y0 = tanhf(y0); y1 = tanhf(y1); y2 = tanhf(y2); y3 = tanhf(y3);
        // MLP1 GEMV + tanh
        float4 b1v = b1s4[sub];
        float z0 = b1v.x, z1 = b1v.y, z2 = b1v.z, z3 = b1v.w;
        gemv64(W1s4, y0, y1, y2, y3, gbase, sub, z0, z1, z2, z3);
        z0 = tanhf(z0); z1 = tanhf(z1); z2 = tanhf(z2); z3 = tanhf(z3);
        // MLP2 (64->32): 2 channels per lane
        float p0 = b2s[2 * sub], p1 = b2s[2 * sub + 1];
#pragma unroll 4
        for (int q = 0; q < 16; q++) {
            int sl = gbase | q;
            float v0 = __shfl_sync(FULL, z0, sl);
            float v1 = __shfl_sync(FULL, z1, sl);
            float v2 = __shfl_sync(FULL, z2, sl);
            float v3 = __shfl_sync(FULL, z3, sl);
            float2 w0 = W2s2[(4 * q + 0) * 16 + sub];
            float2 w1 = W2s2[(4 * q + 1) * 16 + sub];
            float2 w2 = W2s2[(4 * q + 2) * 16 + sub];
            float2 w3 = W2s2[(4 * q + 3) * 16 + sub];
            p0 += v0 * w0.x + v1 * w1.x + v2 * w2.x + v3 * w3.x;
            p1 += v0 * w0.y + v1 * w1.y + v2 * w2.y + v3 * w3.y;
        }
        p0 = tanhf(p0); p1 = tanhf(p1);
        // MLP3 (32->1), reduce within 16-lane group
        float c = p0 * W3s[2 * sub] + p1 * W3s[2 * sub + 1];
#pragma unroll
        for (int o = 8; o > 0; o >>= 1) c += __shfl_xor_sync(FULL, c, o);
        if (valid && sub == 0) {
            int g = batch[node];
            atomicAdd(&g_psum[br * NG + g], c + b3s);
            atomicAdd(&g_pcnt[br * NG + g], 1.0f);
        }
    }
}

// ---------------- final ----------------
__global__ void k_final(float* __restrict__ out) {
    int g = blockIdx.x * blockDim.x + threadIdx.x;
    if (g >= NG) return;
    float ua = g_psum[g]      / fmaxf(g_pcnt[g], 1.f);
    float ub = g_psum[NG + g] / fmaxf(g_pcnt[NG + g], 1.f);
    out[g] = 1.f / (1.f + expf(-(ub - ua)));
}

// ---------------- host orchestration ----------------
extern "C" void kernel_launch(void* const* d_in, const int* in_sizes, int n_in,
                              void* d_out, int out_size) {
    const float* x_a   = (const float*)d_in[0];
    const float* x_b   = (const float*)d_in[1];
    const int*   ei_a  = (const int*)  d_in[2];
    const int*   ei_b  = (const int*)  d_in[3];
    const int*   ba    = (const int*)  d_in[4];
    const int*   bb    = (const int*)  d_in[5];
    const float* Wgat  = (const float*)d_in[6];
    const float* a_src = (const float*)d_in[7];
    const float* a_dst = (const float*)d_in[8];
    const float* bgat  = (const float*)d_in[9];
    const float* Wgcn  = (const float*)d_in[10];
    const float* bgcn  = (const float*)d_in[11];
    const float* W1    = (const float*)d_in[12];
    const float* b1    = (const float*)d_in[13];
    const float* W2    = (const float*)d_in[14];
    const float* b2    = (const float*)d_in[15];
    const float* W3    = (const float*)d_in[16];
    const float* b3    = (const float*)d_in[17];

    dim3 gE((E_TOT + 255) / 256, 2);
    dim3 gS(SCAN_NB, 2);
    dim3 gN((N_NODES + 255) / 256, 2);
    dim3 gW((N_NODES + 7) / 8, 2);      // GAT: 1 node/warp
    dim3 gP1(592, 2);                    // persistent GCN1 (8 blocks/SM)
    dim3 gP2(370, 2);                    // persistent GCN2 (5 blocks/SM by smem)

    k_pre<<<(2 * N_NODES + 255) / 256, 256>>>(Wgat, a_src, a_dst);
    k_deg<<<gE, 256>>>(ei_a, ei_b);
    k_scan1<<<gS, SCAN_B>>>();
    k_scan3<<<gN, 256>>>(x_a, x_b);
    k_fill<<<gE, 256>>>(ei_a, ei_b);
    k_gat_gather<<<gW, 256>>>(Wgat, bgat);
    k_gcn1<<<gP1, 256>>>(Wgcn, bgcn);
    k_gcn2_mlp<<<gP2, 256>>>(Wgcn + U * U, bgcn + U, ba, bb,
                             W1, b1, W2, b2, W3, b3);
    k_final<<<2, 256>>>((float*)d_out);
}

// round 13
// speedup vs baseline: 1.8128x; 1.0471x over previous
#include <cuda_runtime.h>
#include <cuda_fp16.h>
#include <math.h>

#define N_NODES 50000
#define N_EDGES 800000
#define E_TOT   850000   // edges + self loops
#define U       64
#define NG      512
#define F_IN    9
#define SCAN_B  1024
#define SCAN_NB ((N_NODES + SCAN_B - 1) / SCAN_B)   // 49
#define NTILES  ((N_NODES + 15) / 16)               // 3125 (16 nodes per block-tile)
#define FULL    0xffffffffu

// ---------------- scratch (device globals; zero-initialized at load) --------
__device__ uint2  g_bufA[2 * N_NODES * 16];   // fp16 features, 64 half per node
__device__ uint2  g_bufB[2 * N_NODES * 16];
__device__ float4 g_xpack[2 * N_NODES * 3];   // [as, x0..x8, pad, pad] per node
__device__ float  g_ad[2 * N_NODES];
__device__ float  g_dinv[2 * N_NODES];
__device__ int    g_deg[2 * N_NODES];         // re-zeroed by k_scan3 each pass
__device__ int    g_rowtmp[2 * N_NODES];
__device__ int    g_rowptr[2 * (N_NODES + 1)];
__device__ int    g_cursor[2 * N_NODES];
__device__ int    g_bsum[2 * SCAN_NB];
__device__ int2   g_ec[2 * E_TOT];            // (src, gcn coef) per CSR slot
__device__ float  g_wa[F_IN], g_wd[F_IN];
__device__ float  g_psum[2 * NG];             // re-zeroed by k_final each pass
__device__ float  g_pcnt[2 * NG];

__device__ __forceinline__ void edge_src_dst(int e, const int* __restrict__ ei,
                                             int& src, int& dst) {
    if (e < N_EDGES) { src = ei[e]; dst = ei[N_EDGES + e]; }
    else             { src = e - N_EDGES; dst = src; }
}

// fast tanh: ~7 SASS inst vs ~15-20 for libm tanhf; rel err ~1e-6
__device__ __forceinline__ float ftanh(float x) {
    float e = __expf(2.f * x);
    return 1.f - __fdividef(2.f, e + 1.f);
}

// ---------------- CSR build ----------------
// k_deg also computes wa/wd (block 0) -- replaces k_pre
__global__ void k_deg(const int* __restrict__ ei_a, const int* __restrict__ ei_b,
                      const float* __restrict__ W, const float* __restrict__ a_src,
                      const float* __restrict__ a_dst) {
    if (blockIdx.x == 0 && blockIdx.y == 0) {
        int t = threadIdx.x;
        if (t < F_IN) {
            float s = 0.f;
            for (int c = 0; c < U; c++) s += W[t * U + c] * a_src[c];
            g_wa[t] = s;
        } else if (t >= 16 && t < 16 + F_IN) {
            int f = t - 16;
            float s = 0.f;
            for (int c = 0; c < U; c++) s += W[f * U + c] * a_dst[c];
            g_wd[f] = s;
        }
    }
    int br = blockIdx.y;
    int e = blockIdx.x * blockDim.x + threadIdx.x;
    if (e >= E_TOT) return;
    const int* ei = br ? ei_b : ei_a;
    int dst = (e < N_EDGES) ? ei[N_EDGES + e] : (e - N_EDGES);
    atomicAdd(&g_deg[br * N_NODES + dst], 1);
}
__global__ void k_scan1() {
    __shared__ int sm[SCAN_B];
    int br = blockIdx.y;
    int t = threadIdx.x;
    int i = blockIdx.x * SCAN_B + t;
    int v = (i < N_NODES) ? g_deg[br * N_NODES + i] : 0;
    sm[t] = v;
    __syncthreads();
#pragma unroll
    for (int off = 1; off < SCAN_B; off <<= 1) {
        int add = (t >= off) ? sm[t - off] : 0;
        __syncthreads();
        sm[t] += add;
        __syncthreads();
    }
    if (i < N_NODES) g_rowtmp[br * N_NODES + i] = sm[t];
    if (t == SCAN_B - 1) g_bsum[br * SCAN_NB + blockIdx.x] = sm[t];
}
// scan3: finalize CSR + dinv + packed [as, x0..x8]; re-zero deg for next pass
__global__ void k_scan3(const float* __restrict__ xa, const float* __restrict__ xb) {
    __shared__ int bsm[SCAN_NB];
    int br = blockIdx.y;
    int t = threadIdx.x;
    if (t < SCAN_NB) bsm[t] = g_bsum[br * SCAN_NB + t];
    __syncthreads();
    int i = blockIdx.x * blockDim.x + t;
    if (i >= N_NODES) return;
    int blk = i / SCAN_B;
    int pre = 0;
    for (int b = 0; b < blk; b++) pre += bsm[b];
    int incl = g_rowtmp[br * N_NODES + i] + pre;
    int d = g_deg[br * N_NODES + i];
    g_deg[br * N_NODES + i] = 0;          // restore zero for next replay
    g_rowptr[br * (N_NODES + 1) + i + 1] = incl;
    g_cursor[br * N_NODES + i] = incl - d;
    g_dinv[br * N_NODES + i] = rsqrtf((float)d);
    if (i == 0) g_rowptr[br * (N_NODES + 1)] = 0;
    const float* x = br ? xb : xa;
    const float* xi = x + i * F_IN;
    float v[F_IN];
    float as = 0.f, ad = 0.f;
#pragma unroll
    for (int f = 0; f < F_IN; f++) {
        v[f] = xi[f];
        as += v[f] * g_wa[f];
        ad += v[f] * g_wd[f];
    }
    g_ad[br * N_NODES + i] = ad;
    float4* xp = g_xpack + ((size_t)br * N_NODES + i) * 3;
    xp[0] = make_float4(as, v[0], v[1], v[2]);
    xp[1] = make_float4(v[3], v[4], v[5], v[6]);
    xp[2] = make_float4(v[7], v[8], 0.f, 0.f);
}
// fill: CSR slot gets (src, precomputed GCN coefficient)
__global__ void k_fill(const int* __restrict__ ei_a, const int* __restrict__ ei_b) {
    int br = blockIdx.y;
    int e = blockIdx.x * blockDim.x + threadIdx.x;
    if (e >= E_TOT) return;
    const int* ei = br ? ei_b : ei_a;
    int src, dst; edge_src_dst(e, ei, src, dst);
    int pos = atomicAdd(&g_cursor[br * N_NODES + dst], 1);
    float coef = g_dinv[br * N_NODES + src] * g_dinv[br * N_NODES + dst];
    g_ec[br * E_TOT + pos] = make_int2(src, __float_as_int(coef));
}

// ---------------- GAT: softmax-weighted aggregate of packed x, then @W ------
__global__ void k_gat_gather(const float* __restrict__ W, const float* __restrict__ b) {
    __shared__ float Ws[F_IN * U];
    __shared__ float bs[U];
    int tid = threadIdx.x;
    for (int i = tid; i < F_IN * U; i += blockDim.x) Ws[i] = W[i];
    if (tid < U) bs[tid] = b[tid];
    __syncthreads();
    int br = blockIdx.y;
    int lane = tid & 31;
    int node = blockIdx.x * (blockDim.x >> 5) + (tid >> 5);
    if (node >= N_NODES) return;
    const int2*   ec = g_ec + br * E_TOT;
    const int*    rp = g_rowptr + br * (N_NODES + 1);
    const float4* xp = g_xpack + (size_t)br * N_NODES * 3;
    int k0 = rp[node], k1 = rp[node + 1];
    float ad_n = g_ad[br * N_NODES + node];
    float acc[F_IN] = {0, 0, 0, 0, 0, 0, 0, 0, 0};
    float ssum = 0.f;
    for (int k = k0 + lane; k < k1; k += 32) {
        int s = ec[k].x;
        float4 p0 = xp[s * 3 + 0];
        float4 p1 = xp[s * 3 + 1];
        float4 p2 = xp[s * 3 + 2];
        float e = p0.x + ad_n;           // p0.x = as[s]
        e = e > 0.f ? e : 0.2f * e;
        e = fminf(e, 80.f);
        float ex = __expf(e);
        ssum += ex;
        acc[0] += ex * p0.y; acc[1] += ex * p0.z; acc[2] += ex * p0.w;
        acc[3] += ex * p1.x; acc[4] += ex * p1.y; acc[5] += ex * p1.z;
        acc[6] += ex * p1.w; acc[7] += ex * p2.x; acc[8] += ex * p2.y;
    }
#pragma unroll
    for (int o = 16; o > 0; o >>= 1) {
        ssum += __shfl_xor_sync(FULL, ssum, o);
#pragma unroll
        for (int f = 0; f < F_IN; f++) acc[f] += __shfl_xor_sync(FULL, acc[f], o);
    }
    float inv = 1.f / ssum;
    int c0 = 2 * lane;
    float y0 = bs[c0], y1 = bs[c0 + 1];
#pragma unroll
    for (int f = 0; f < F_IN; f++) {
        float v = acc[f] * inv;
        y0 += v * Ws[f * U + c0];
        y1 += v * Ws[f * U + c0 + 1];
    }
    __half2* out2 = reinterpret_cast<__half2*>(g_bufA) + ((size_t)br * N_NODES + node) * 32;
    out2[lane] = __floats2half2_rn(ftanh(y0), ftanh(y1));
}

// GEMV via smem-broadcast x: stage 4 accum/lane, then per q: 1 LDS.128 (x bcast)
// + 4 LDS.128 (W) + 16 FFMA. Two halves read addrs 68 floats apart -> bank-free.
#define STAGE_F 136   // floats per warp stage: node0 @0, node1 @68 (pad 4)
__device__ __forceinline__ void gemv64(const float4* __restrict__ Wsm,
                                       float* stage, int half_off, int sub,
                                       float v0, float v1, float v2, float v3,
                                       float& y0, float& y1, float& y2, float& y3) {
    *reinterpret_cast<float4*>(stage + half_off + sub * 4) = make_float4(v0, v1, v2, v3);
    __syncwarp();
    const float* xs = stage + half_off;
#pragma unroll 4
    for (int q = 0; q < 16; q++) {
        float4 xv = *reinterpret_cast<const float4*>(xs + q * 4);
        float4 w0 = Wsm[(4 * q + 0) * 16 + sub];
        float4 w1 = Wsm[(4 * q + 1) * 16 + sub];
        float4 w2 = Wsm[(4 * q + 2) * 16 + sub];
        float4 w3 = Wsm[(4 * q + 3) * 16 + sub];
        y0 += xv.x * w0.x + xv.y * w1.x + xv.z * w2.x + xv.w * w3.x;
        y1 += xv.x * w0.y + xv.y * w1.y + xv.z * w2.y + xv.w * w3.y;
        y2 += xv.x * w0.z + xv.y * w1.z + xv.z * w2.z + xv.w * w3.z;
        y3 += xv.x * w0.w + xv.y * w1.w + xv.z * w2.w + xv.w * w3.w;
    }
    __syncwarp();   // WAR guard before next staging round
}

// gather core for one node pair: returns 4-channel accumulators
__device__ __forceinline__ void gcn_edge_gather(const int2* __restrict__ ec,
                                                const int* __restrict__ rp,
                                                const uint2* __restrict__ x4,
                                                int node, bool valid,
                                                int gbase, int sub,
                                                float& a0, float& a1, float& a2, float& a3) {
    int k0 = 0, k1 = 0;
    if (valid) { k0 = rp[node]; k1 = rp[node + 1]; }
    int trips = (k1 - k0 + 15) >> 4;
    trips = max(trips, __shfl_xor_sync(FULL, trips, 16));
    a0 = 0.f; a1 = 0.f; a2 = 0.f; a3 = 0.f;
    for (int t = 0; t < trips; t++) {
        int k = k0 + t * 16 + sub;
        int2 e_l = make_int2(0, 0);      // coef 0 -> padding contributes nothing
        if (k < k1) e_l = ec[k];
#pragma unroll
        for (int j = 0; j < 16; j++) {
            int sl = gbase | j;
            int   s  = __shfl_sync(FULL, e_l.x, sl);
            float cf = __uint_as_float(__shfl_sync(FULL, e_l.y, sl));
            uint2 v = x4[s * 16 + sub];
            float2 f0 = __half22float2(*(__half2*)&v.x);
            float2 f1 = __half22float2(*(__half2*)&v.y);
            a0 += cf * f0.x; a1 += cf * f0.y;
            a2 += cf * f1.x; a3 += cf * f1.y;
        }
    }
}

// ---------------- GCN layer 1: persistent, 2 nodes/warp, bufA -> bufB --------
__global__ void __launch_bounds__(256) k_gcn1(const float* __restrict__ W,
                                              const float* __restrict__ b) {
    __shared__ float4 Ws4[U * U / 4];
    __shared__ float4 bs4[U / 4];
    __shared__ __align__(16) float xstage[8][STAGE_F];
    int tid = threadIdx.x;
    for (int i = tid; i < U * U; i += blockDim.x) ((float*)Ws4)[i] = W[i];
    if (tid < U) ((float*)bs4)[tid] = b[tid];
    __syncthreads();
    int br = blockIdx.y;
    int lane = tid & 31, warp = tid >> 5;
    int sub = lane & 15, gbase = lane & 16;
    int half_off = (lane >> 4) * 68;
    float* stage = xstage[warp];
    const int2*  ec = g_ec + br * E_TOT;
    const int*   rp = g_rowptr + br * (N_NODES + 1);
    const uint2* x4 = g_bufA + (size_t)br * N_NODES * 16;
    uint2* outb = g_bufB + (size_t)br * N_NODES * 16;
    for (int tile = blockIdx.x; tile < NTILES; tile += gridDim.x) {
        int node = (tile * 8 + warp) * 2 + (lane >> 4);
        bool valid = node < N_NODES;
        float a0, a1, a2, a3;
        gcn_edge_gather(ec, rp, x4, node, valid, gbase, sub, a0, a1, a2, a3);
        float4 bv = bs4[sub];
        float y0 = bv.x, y1 = bv.y, y2 = bv.z, y3 = bv.w;
        gemv64(Ws4, stage, half_off, sub, a0, a1, a2, a3, y0, y1, y2, y3);
        if (valid) {
            __half2 h0 = __floats2half2_rn(ftanh(y0), ftanh(y1));
            __half2 h1 = __floats2half2_rn(ftanh(y2), ftanh(y3));
            uint2 o;
            o.x = *(unsigned*)&h0; o.y = *(unsigned*)&h1;
            outb[node * 16 + sub] = o;
        }
    }
}

// ---------------- GCN layer 2 + MLP + mean-pool, persistent, 2 nodes/warp ----
__global__ void __launch_bounds__(256) k_gcn2_mlp(
                           const float* __restrict__ W, const float* __restrict__ b,
                           const int* __restrict__ ba, const int* __restrict__ bb,
                           const float* __restrict__ W1, const float* __restrict__ b1,
                           const float* __restrict__ W2, const float* __restrict__ b2,
                           const float* __restrict__ W3, const float* __restrict__ b3) {
    __shared__ float4 Ws4[U * U / 4], W1s4[U * U / 4];
    __shared__ float2 W2s2[U * 16];
    __shared__ float4 bs4[U / 4], b1s4[U / 4];
    __shared__ float  b2s[32], W3s[32], b3s;
    __shared__ __align__(16) float xstage[8][STAGE_F];
    int tid = threadIdx.x;
    for (int i = tid; i < U * U; i += blockDim.x) {
        ((float*)Ws4)[i] = W[i];
        ((float*)W1s4)[i] = W1[i];
    }
    for (int i = tid; i < U * 32; i += blockDim.x) ((float*)W2s2)[i] = W2[i];
    if (tid < U)  { ((float*)bs4)[tid] = b[tid]; ((float*)b1s4)[tid] = b1[tid]; }
    if (tid < 32) { b2s[tid] = b2[tid]; W3s[tid] = W3[tid]; }
    if (tid == 0) b3s = b3[0];
    __syncthreads();
    int br = blockIdx.y;
    int lane = tid & 31, warp = tid >> 5;
    int sub = lane & 15, gbase = lane & 16;
    int half_off = (lane >> 4) * 68;
    float* stage = xstage[warp];
    const int2*  ec = g_ec + br * E_TOT;
    const int*   rp = g_rowptr + br * (N_NODES + 1);
    const uint2* x4 = g_bufB + (size_t)br * N_NODES * 16;
    const int* batch = br ? bb : ba;
    for (int tile = blockIdx.x; tile < NTILES; tile += gridDim.x) {
        int node = (tile * 8 + warp) * 2 + (lane >> 4);
        bool valid = node < N_NODES;
        float a0, a1, a2, a3;
        gcn_edge_gather(ec, rp, x4, node, valid, gbase, sub, a0, a1, a2, a3);
        // GCN GEMV + tanh
        float4 bv = bs4[sub];
        float y0 = bv.x, y1 = bv.y, y2 = bv.z, y3 = bv.w;
        gemv64(Ws4, stage, half_off, sub, a0, a1, a2, a3, y0, y1, y2, y3);
        y0 = ftanh(y0); y1 = ftanh(y1); y2 = ftanh(y2); y3 = ftanh(y3);
        // MLP1 GEMV + tanh
        float4 b1v = b1s4[sub];
        float z0 = b1v.x, z1 = b1v.y, z2 = b1v.z, z3 = b1v.w;
        gemv64(W1s4, stage, half_off, sub, y0, y1, y2, y3, z0, z1, z2, z3);
        z0 = ftanh(z0); z1 = ftanh(z1); z2 = ftanh(z2); z3 = ftanh(z3);
        // MLP2 (64->32): stage z, broadcast-read per q
        *reinterpret_cast<float4*>(stage + half_off + sub * 4) =
            make_float4(z0, z1, z2, z3);
        __syncwarp();
        float p0 = b2s[2 * sub], p1 = b2s[2 * sub + 1];
        const float* zs = stage + half_off;
#pragma unroll 4
        for (int q = 0; q < 16; q++) {
            float4 zv = *reinterpret_cast<const float4*>(zs + q * 4);
            float2 w0 = W2s2[(4 * q + 0) * 16 + sub];
            float2 w1 = W2s2[(4 * q + 1) * 16 + sub];
            float2 w2 = W2s2[(4 * q + 2) * 16 + sub];
            float2 w3 = W2s2[(4 * q + 3) * 16 + sub];
            p0 += zv.x * w0.x + zv.y * w1.x + zv.z * w2.x + zv.w * w3.x;
            p1 += zv.x * w0.y + zv.y * w1.y + zv.z * w2.y + zv.w * w3.y;
        }
        __syncwarp();
        p0 = ftanh(p0); p1 = ftanh(p1);
        // MLP3 (32->1), reduce within 16-lane group
        float c = p0 * W3s[2 * sub] + p1 * W3s[2 * sub + 1];
#pragma unroll
        for (int o = 8; o > 0; o >>= 1) c += __shfl_xor_sync(FULL, c, o);
        if (valid && sub == 0) {
            int g = batch[node];
            atomicAdd(&g_psum[br * NG + g], c + b3s);
            atomicAdd(&g_pcnt[br * NG + g], 1.0f);
        }
    }
}

// ---------------- final: output + restore pool zeros for next replay --------
__global__ void k_final(float* __restrict__ out) {
    int g = blockIdx.x * blockDim.x + threadIdx.x;
    if (g >= NG) return;
    float ua = g_psum[g]      / fmaxf(g_pcnt[g], 1.f);
    float ub = g_psum[NG + g] / fmaxf(g_pcnt[NG + g], 1.f);
    out[g] = 1.f / (1.f + expf(-(ub - ua)));
    g_psum[g] = 0.f; g_psum[NG + g] = 0.f;
    g_pcnt[g] = 0.f; g_pcnt[NG + g] = 0.f;
}

// ---------------- host orchestration ----------------
extern "C" void kernel_launch(void* const* d_in, const int* in_sizes, int n_in,
                              void* d_out, int out_size) {
    const float* x_a   = (const float*)d_in[0];
    const float* x_b   = (const float*)d_in[1];
    const int*   ei_a  = (const int*)  d_in[2];
    const int*   ei_b  = (const int*)  d_in[3];
    const int*   ba    = (const int*)  d_in[4];
    const int*   bb    = (const int*)  d_in[5];
    const float* Wgat  = (const float*)d_in[6];
    const float* a_src = (const float*)d_in[7];
    const float* a_dst = (const float*)d_in[8];
    const float* bgat  = (const float*)d_in[9];
    const float* Wgcn  = (const float*)d_in[10];
    const float* bgcn  = (const float*)d_in[11];
    const float* W1    = (const float*)d_in[12];
    const float* b1    = (const float*)d_in[13];
    const float* W2    = (const float*)d_in[14];
    const float* b2    = (const float*)d_in[15];
    const float* W3    = (const float*)d_in[16];
    const float* b3    = (const float*)d_in[17];

    dim3 gE((E_TOT + 255) / 256, 2);
    dim3 gS(SCAN_NB, 2);
    dim3 gN((N_NODES + 255) / 256, 2);
    dim3 gW((N_NODES + 7) / 8, 2);      // GAT: 1 node/warp
    dim3 gP1(592, 2);                    // persistent GCN1 (8 blocks/SM)
    dim3 gP2(296, 2);                    // persistent GCN2 (4 blocks/SM by smem)

    k_deg<<<gE, 256>>>(ei_a, ei_b, Wgat, a_src, a_dst);
    k_scan1<<<gS, SCAN_B>>>();
    k_scan3<<<gN, 256>>>(x_a, x_b);
    k_fill<<<gE, 256>>>(ei_a, ei_b);
    k_gat_gather<<<gW, 256>>>(Wgat, bgat);
    k_gcn1<<<gP1, 256>>>(Wgcn, bgcn);
    k_gcn2_mlp<<<gP2, 256>>>(Wgcn + U * U, bgcn + U, ba, bb,
                             W1, b1, W2, b2, W3, b3);
    k_final<<<2, 256>>>((float*)d_out);
}

// round 14
// speedup vs baseline: 1.8985x; 1.0473x over previous
#include <cuda_runtime.h>
#include <cuda_fp16.h>
#include <math.h>

#define N_NODES 50000
#define NSTR    (N_NODES + 1)   // feature-row stride; row N_NODES = reserved zero row
#define N_EDGES 800000
#define E_TOT   850000          // edges + self loops
#define U       64
#define NG      512
#define F_IN    9
#define SCAN_B  1024
#define SCAN_NB ((N_NODES + SCAN_B - 1) / SCAN_B)   // 49
#define NTILES  ((N_NODES + 15) / 16)               // 3125 (16 nodes per block-tile)
#define FULL    0xffffffffu

// ---------------- scratch (device globals; zero-initialized at load) --------
__device__ uint2  g_bufA[2 * NSTR * 16];      // fp16 features*dinv; row N_NODES stays 0
__device__ uint2  g_bufB[2 * NSTR * 16];
__device__ float4 g_xpack[2 * N_NODES * 3];   // [as, x0..x8, pad, pad] per node
__device__ float  g_ad[2 * N_NODES];
__device__ float  g_dinv[2 * N_NODES];
__device__ int    g_deg[2 * N_NODES];         // re-zeroed by k_scan3 each pass
__device__ int    g_rowtmp[2 * N_NODES];
__device__ int    g_rowptr[2 * (N_NODES + 1)];
__device__ int    g_cursor[2 * N_NODES];
__device__ int    g_bsum[2 * SCAN_NB];
__device__ int    g_csrc[2 * E_TOT];          // src per CSR slot
__device__ float  g_wa[F_IN], g_wd[F_IN];
__device__ float  g_psum[2 * NG];             // re-zeroed by k_final each pass
__device__ float  g_pcnt[2 * NG];

__device__ __forceinline__ void edge_src_dst(int e, const int* __restrict__ ei,
                                             int& src, int& dst) {
    if (e < N_EDGES) { src = ei[e]; dst = ei[N_EDGES + e]; }
    else             { src = e - N_EDGES; dst = src; }
}

// fast tanh: ~7 SASS inst; rel err ~1e-6
__device__ __forceinline__ float ftanh(float x) {
    float e = __expf(2.f * x);
    return 1.f - __fdividef(2.f, e + 1.f);
}

// ---------------- CSR build ----------------
__global__ void k_deg(const int* __restrict__ ei_a, const int* __restrict__ ei_b,
                      const float* __restrict__ W, const float* __restrict__ a_src,
                      const float* __restrict__ a_dst) {
    if (blockIdx.x == 0 && blockIdx.y == 0) {
        int t = threadIdx.x;
        if (t < F_IN) {
            float s = 0.f;
            for (int c = 0; c < U; c++) s += W[t * U + c] * a_src[c];
            g_wa[t] = s;
        } else if (t >= 16 && t < 16 + F_IN) {
            int f = t - 16;
            float s = 0.f;
            for (int c = 0; c < U; c++) s += W[f * U + c] * a_dst[c];
            g_wd[f] = s;
        }
    }
    int br = blockIdx.y;
    int e = blockIdx.x * blockDim.x + threadIdx.x;
    if (e >= E_TOT) return;
    const int* ei = br ? ei_b : ei_a;
    int dst = (e < N_EDGES) ? ei[N_EDGES + e] : (e - N_EDGES);
    atomicAdd(&g_deg[br * N_NODES + dst], 1);
}
__global__ void k_scan1() {
    __shared__ int sm[SCAN_B];
    int br = blockIdx.y;
    int t = threadIdx.x;
    int i = blockIdx.x * SCAN_B + t;
    int v = (i < N_NODES) ? g_deg[br * N_NODES + i] : 0;
    sm[t] = v;
    __syncthreads();
#pragma unroll
    for (int off = 1; off < SCAN_B; off <<= 1) {
        int add = (t >= off) ? sm[t - off] : 0;
        __syncthreads();
        sm[t] += add;
        __syncthreads();
    }
    if (i < N_NODES) g_rowtmp[br * N_NODES + i] = sm[t];
    if (t == SCAN_B - 1) g_bsum[br * SCAN_NB + blockIdx.x] = sm[t];
}
// scan3: finalize CSR + dinv + packed [as, x0..x8]; re-zero deg for next pass
__global__ void k_scan3(const float* __restrict__ xa, const float* __restrict__ xb) {
    __shared__ int bsm[SCAN_NB];
    int br = blockIdx.y;
    int t = threadIdx.x;
    if (t < SCAN_NB) bsm[t] = g_bsum[br * SCAN_NB + t];
    __syncthreads();
    int i = blockIdx.x * blockDim.x + t;
    if (i >= N_NODES) return;
    int blk = i / SCAN_B;
    int pre = 0;
    for (int b = 0; b < blk; b++) pre += bsm[b];
    int incl = g_rowtmp[br * N_NODES + i] + pre;
    int d = g_deg[br * N_NODES + i];
    g_deg[br * N_NODES + i] = 0;          // restore zero for next replay
    g_rowptr[br * (N_NODES + 1) + i + 1] = incl;
    g_cursor[br * N_NODES + i] = incl - d;
    g_dinv[br * N_NODES + i] = rsqrtf((float)d);
    if (i == 0) g_rowptr[br * (N_NODES + 1)] = 0;
    const float* x = br ? xb : xa;
    const float* xi = x + i * F_IN;
    float v[F_IN];
    float as = 0.f, ad = 0.f;
#pragma unroll
    for (int f = 0; f < F_IN; f++) {
        v[f] = xi[f];
        as += v[f] * g_wa[f];
        ad += v[f] * g_wd[f];
    }
    g_ad[br * N_NODES + i] = ad;
    float4* xp = g_xpack + ((size_t)br * N_NODES + i) * 3;
    xp[0] = make_float4(as, v[0], v[1], v[2]);
    xp[1] = make_float4(v[3], v[4], v[5], v[6]);
    xp[2] = make_float4(v[7], v[8], 0.f, 0.f);
}
// fill: CSR slot gets src only (coefficients folded into features)
__global__ void k_fill(const int* __restrict__ ei_a, const int* __restrict__ ei_b) {
    int br = blockIdx.y;
    int e = blockIdx.x * blockDim.x + threadIdx.x;
    if (e >= E_TOT) return;
    const int* ei = br ? ei_b : ei_a;
    int src, dst; edge_src_dst(e, ei, src, dst);
    int pos = atomicAdd(&g_cursor[br * N_NODES + dst], 1);
    g_csrc[br * E_TOT + pos] = src;
}

// ---------------- GAT: softmax aggregate of packed x, then @W; out *= dinv --
__global__ void k_gat_gather(const float* __restrict__ W, const float* __restrict__ b) {
    __shared__ float Ws[F_IN * U];
    __shared__ float bs[U];
    int tid = threadIdx.x;
    for (int i = tid; i < F_IN * U; i += blockDim.x) Ws[i] = W[i];
    if (tid < U) bs[tid] = b[tid];
    __syncthreads();
    int br = blockIdx.y;
    int lane = tid & 31;
    int node = blockIdx.x * (blockDim.x >> 5) + (tid >> 5);
    if (node >= N_NODES) return;
    const int*    cs = g_csrc + br * E_TOT;
    const int*    rp = g_rowptr + br * (N_NODES + 1);
    const float4* xp = g_xpack + (size_t)br * N_NODES * 3;
    int k0 = rp[node], k1 = rp[node + 1];
    float ad_n = g_ad[br * N_NODES + node];
    float acc[F_IN] = {0, 0, 0, 0, 0, 0, 0, 0, 0};
    float ssum = 0.f;
    for (int k = k0 + lane; k < k1; k += 32) {
        int s = cs[k];
        float4 p0 = xp[s * 3 + 0];
        float4 p1 = xp[s * 3 + 1];
        float4 p2 = xp[s * 3 + 2];
        float e = p0.x + ad_n;           // p0.x = as[s]
        e = e > 0.f ? e : 0.2f * e;
        e = fminf(e, 80.f);
        float ex = __expf(e);
        ssum += ex;
        acc[0] += ex * p0.y; acc[1] += ex * p0.z; acc[2] += ex * p0.w;
        acc[3] += ex * p1.x; acc[4] += ex * p1.y; acc[5] += ex * p1.z;
        acc[6] += ex * p1.w; acc[7] += ex * p2.x; acc[8] += ex * p2.y;
    }
#pragma unroll
    for (int o = 16; o > 0; o >>= 1) {
        ssum += __shfl_xor_sync(FULL, ssum, o);
#pragma unroll
        for (int f = 0; f < F_IN; f++) acc[f] += __shfl_xor_sync(FULL, acc[f], o);
    }
    float inv = 1.f / ssum;
    int c0 = 2 * lane;
    float y0 = bs[c0], y1 = bs[c0 + 1];
#pragma unroll
    for (int f = 0; f < F_IN; f++) {
        float v = acc[f] * inv;
        y0 += v * Ws[f * U + c0];
        y1 += v * Ws[f * U + c0 + 1];
    }
    float dn = g_dinv[br * N_NODES + node];   // pre-scale for GCN1's gather
    __half2* out2 = reinterpret_cast<__half2*>(g_bufA) + ((size_t)br * NSTR + node) * 32;
    out2[lane] = __floats2half2_rn(ftanh(y0) * dn, ftanh(y1) * dn);
}

// GEMV via smem-broadcast x (16B-aligned stage; offsets 0/68 floats bank-free)
#define STAGE_F 136
__device__ __forceinline__ void gemv64(const float4* __restrict__ Wsm,
                                       float* stage, int half_off, int sub,
                                       float v0, float v1, float v2, float v3,
                                       float& y0, float& y1, float& y2, float& y3) {
    *reinterpret_cast<float4*>(stage + half_off + sub * 4) = make_float4(v0, v1, v2, v3);
    __syncwarp();
    const float* xs = stage + half_off;
#pragma unroll 4
    for (int q = 0; q < 16; q++) {
        float4 xv = *reinterpret_cast<const float4*>(xs + q * 4);
        float4 w0 = Wsm[(4 * q + 0) * 16 + sub];
        float4 w1 = Wsm[(4 * q + 1) * 16 + sub];
        float4 w2 = Wsm[(4 * q + 2) * 16 + sub];
        float4 w3 = Wsm[(4 * q + 3) * 16 + sub];
        y0 += xv.x * w0.x + xv.y * w1.x + xv.z * w2.x + xv.w * w3.x;
        y1 += xv.x * w0.y + xv.y * w1.y + xv.z * w2.y + xv.w * w3.y;
        y2 += xv.x * w0.z + xv.y * w1.z + xv.z * w2.z + xv.w * w3.z;
        y3 += xv.x * w0.w + xv.y * w1.w + xv.z * w2.w + xv.w * w3.w;
    }
    __syncwarp();   // WAR guard before next staging round
}

// gather core: plain sum of pre-scaled features; padding -> zero row N_NODES
__device__ __forceinline__ void gcn_edge_gather(const int* __restrict__ cs,
                                                const int* __restrict__ rp,
                                                const uint2* __restrict__ x4,
                                                int node, bool valid,
                                                int gbase, int sub,
                                                float& a0, float& a1, float& a2, float& a3) {
    int k0 = 0, k1 = 0;
    if (valid) { k0 = rp[node]; k1 = rp[node + 1]; }
    int trips = (k1 - k0 + 15) >> 4;
    trips = max(trips, __shfl_xor_sync(FULL, trips, 16));
    a0 = 0.f; a1 = 0.f; a2 = 0.f; a3 = 0.f;
    for (int t = 0; t < trips; t++) {
        int k = k0 + t * 16 + sub;
        int s_l = (k < k1) ? cs[k] : N_NODES;   // zero row for padding
#pragma unroll
        for (int j = 0; j < 16; j++) {
            int s = __shfl_sync(FULL, s_l, gbase | j);
            uint2 v = x4[s * 16 + sub];
            float2 f0 = __half22float2(*(__half2*)&v.x);
            float2 f1 = __half22float2(*(__half2*)&v.y);
            a0 += f0.x; a1 += f0.y;
            a2 += f1.x; a3 += f1.y;
        }
    }
}

// ---------------- GCN layer 1: persistent, 2 nodes/warp, bufA -> bufB --------
__global__ void __launch_bounds__(256) k_gcn1(const float* __restrict__ W,
                                              const float* __restrict__ b) {
    __shared__ float4 Ws4[U * U / 4];
    __shared__ float4 bs4[U / 4];
    __shared__ __align__(16) float xstage[8][STAGE_F];
    int tid = threadIdx.x;
    for (int i = tid; i < U * U; i += blockDim.x) ((float*)Ws4)[i] = W[i];
    if (tid < U) ((float*)bs4)[tid] = b[tid];
    __syncthreads();
    int br = blockIdx.y;
    int lane = tid & 31, warp = tid >> 5;
    int sub = lane & 15, gbase = lane & 16;
    int half_off = (lane >> 4) * 68;
    float* stage = xstage[warp];
    const int*   cs = g_csrc + br * E_TOT;
    const int*   rp = g_rowptr + br * (N_NODES + 1);
    const float* dinv = g_dinv + br * N_NODES;
    const uint2* x4 = g_bufA + (size_t)br * NSTR * 16;
    uint2* outb = g_bufB + (size_t)br * NSTR * 16;
    for (int tile = blockIdx.x; tile < NTILES; tile += gridDim.x) {
        int node = (tile * 8 + warp) * 2 + (lane >> 4);
        bool valid = node < N_NODES;
        float dn = valid ? dinv[node] : 0.f;
        float a0, a1, a2, a3;
        gcn_edge_gather(cs, rp, x4, node, valid, gbase, sub, a0, a1, a2, a3);
        a0 *= dn; a1 *= dn; a2 *= dn; a3 *= dn;
        float4 bv = bs4[sub];
        float y0 = bv.x, y1 = bv.y, y2 = bv.z, y3 = bv.w;
        gemv64(Ws4, stage, half_off, sub, a0, a1, a2, a3, y0, y1, y2, y3);
        if (valid) {
            __half2 h0 = __floats2half2_rn(ftanh(y0) * dn, ftanh(y1) * dn);
            __half2 h1 = __floats2half2_rn(ftanh(y2) * dn, ftanh(y3) * dn);
            uint2 o;
            o.x = *(unsigned*)&h0; o.y = *(unsigned*)&h1;
            outb[node * 16 + sub] = o;
        }
    }
}

// ---------------- GCN layer 2 + MLP + mean-pool, persistent, 2 nodes/warp ----
__global__ void __launch_bounds__(256) k_gcn2_mlp(
                           const float* __restrict__ W, const float* __restrict__ b,
                           const int* __restrict__ ba, const int* __restrict__ bb,
                           const float* __restrict__ W1, const float* __restrict__ b1,
                           const float* __restrict__ W2, const float* __restrict__ b2,
                           const float* __restrict__ W3, const float* __restrict__ b3) {
    __shared__ float4 Ws4[U * U / 4], W1s4[U * U / 4];
    __shared__ float2 W2s2[U * 16];
    __shared__ float4 bs4[U / 4], b1s4[U / 4];
    __shared__ float  b2s[32], W3s[32], b3s;
    __shared__ __align__(16) float xstage[8][STAGE_F];
    int tid = threadIdx.x;
    for (int i = tid; i < U * U; i += blockDim.x) {
        ((float*)Ws4)[i] = W[i];
        ((float*)W1s4)[i] = W1[i];
    }
    for (int i = tid; i < U * 32; i += blockDim.x) ((float*)W2s2)[i] = W2[i];
    if (tid < U)  { ((float*)bs4)[tid] = b[tid]; ((float*)b1s4)[tid] = b1[tid]; }
    if (tid < 32) { b2s[tid] = b2[tid]; W3s[tid] = W3[tid]; }
    if (tid == 0) b3s = b3[0];
    __syncthreads();
    int br = blockIdx.y;
    int lane = tid & 31, warp = tid >> 5;
    int sub = lane & 15, gbase = lane & 16;
    int half_off = (lane >> 4) * 68;
    float* stage = xstage[warp];
    const int*   cs = g_csrc + br * E_TOT;
    const int*   rp = g_rowptr + br * (N_NODES + 1);
    const float* dinv = g_dinv + br * N_NODES;
    const uint2* x4 = g_bufB + (size_t)br * NSTR * 16;
    const int* batch = br ? bb : ba;
    for (int tile = blockIdx.x; tile < NTILES; tile += gridDim.x) {
        int node = (tile * 8 + warp) * 2 + (lane >> 4);
        bool valid = node < N_NODES;
        float dn = valid ? dinv[node] : 0.f;
        float a0, a1, a2, a3;
        gcn_edge_gather(cs, rp, x4, node, valid, gbase, sub, a0, a1, a2, a3);
        a0 *= dn; a1 *= dn; a2 *= dn; a3 *= dn;
        // GCN GEMV + tanh
        float4 bv = bs4[sub];
        float y0 = bv.x, y1 = bv.y, y2 = bv.z, y3 = bv.w;
        gemv64(Ws4, stage, half_off, sub, a0, a1, a2, a3, y0, y1, y2, y3);
        y0 = ftanh(y0); y1 = ftanh(y1); y2 = ftanh(y2); y3 = ftanh(y3);
        // MLP1 GEMV + tanh
        float4 b1v = b1s4[sub];
        float z0 = b1v.x, z1 = b1v.y, z2 = b1v.z, z3 = b1v.w;
        gemv64(W1s4, stage, half_off, sub, y0, y1, y2, y3, z0, z1, z2, z3);
        z0 = ftanh(z0); z1 = ftanh(z1); z2 = ftanh(z2); z3 = ftanh(z3);
        // MLP2 (64->32): stage z, broadcast-read per q
        *reinterpret_cast<float4*>(stage + half_off + sub * 4) =
            make_float4(z0, z1, z2, z3);
        __syncwarp();
        float p0 = b2s[2 * sub], p1 = b2s[2 * sub + 1];
        const float* zs = stage + half_off;
#pragma unroll 4
        for (int q = 0; q < 16; q++) {
            float4 zv = *reinterpret_cast<const float4*>(zs + q * 4);
            float2 w0 = W2s2[(4 * q + 0) * 16 + sub];
            float2 w1 = W2s2[(4 * q + 1) * 16 + sub];
            float2 w2 = W2s2[(4 * q + 2) * 16 + sub];
            float2 w3 = W2s2[(4 * q + 3) * 16 + sub];
            p0 += zv.x * w0.x + zv.y * w1.x + zv.z * w2.x + zv.w * w3.x;
            p1 += zv.x * w0.y + zv.y * w1.y + zv.z * w2.y + zv.w * w3.y;
        }
        __syncwarp();
        p0 = ftanh(p0); p1 = ftanh(p1);
        // MLP3 (32->1), reduce within 16-lane group
        float c = p0 * W3s[2 * sub] + p1 * W3s[2 * sub + 1];
#pragma unroll
        for (int o = 8; o > 0; o >>= 1) c += __shfl_xor_sync(FULL, c, o);
        if (valid && sub == 0) {
            int g = batch[node];
            atomicAdd(&g_psum[br * NG + g], c + b3s);
            atomicAdd(&g_pcnt[br * NG + g], 1.0f);
        }
    }
}

// ---------------- final: output + restore pool zeros for next replay --------
__global__ void k_final(float* __restrict__ out) {
    int g = blockIdx.x * blockDim.x + threadIdx.x;
    if (g >= NG) return;
    float ua = g_psum[g]      / fmaxf(g_pcnt[g], 1.f);
    float ub = g_psum[NG + g] / fmaxf(g_pcnt[NG + g], 1.f);
    out[g] = 1.f / (1.f + expf(-(ub - ua)));
    g_psum[g] = 0.f; g_psum[NG + g] = 0.f;
    g_pcnt[g] = 0.f; g_pcnt[NG + g] = 0.f;
}

// ---------------- host orchestration ----------------
extern "C" void kernel_launch(void* const* d_in, const int* in_sizes, int n_in,
                              void* d_out, int out_size) {
    const float* x_a   = (const float*)d_in[0];
    const float* x_b   = (const float*)d_in[1];
    const int*   ei_a  = (const int*)  d_in[2];
    const int*   ei_b  = (const int*)  d_in[3];
    const int*   ba    = (const int*)  d_in[4];
    const int*   bb    = (const int*)  d_in[5];
    const float* Wgat  = (const float*)d_in[6];
    const float* a_src = (const float*)d_in[7];
    const float* a_dst = (const float*)d_in[8];
    const float* bgat  = (const float*)d_in[9];
    const float* Wgcn  = (const float*)d_in[10];
    const float* bgcn  = (const float*)d_in[11];
    const float* W1    = (const float*)d_in[12];
    const float* b1    = (const float*)d_in[13];
    const float* W2    = (const float*)d_in[14];
    const float* b2    = (const float*)d_in[15];
    const float* W3    = (const float*)d_in[16];
    const float* b3    = (const float*)d_in[17];

    dim3 gE((E_TOT + 255) / 256, 2);
    dim3 gS(SCAN_NB, 2);
    dim3 gN((N_NODES + 255) / 256, 2);
    dim3 gW((N_NODES + 7) / 8, 2);      // GAT: 1 node/warp
    dim3 gP1(592, 2);                    // persistent GCN1 (8 blocks/SM)
    dim3 gP2(296, 2);                    // persistent GCN2 (4 blocks/SM by smem)

    k_deg<<<gE, 256>>>(ei_a, ei_b, Wgat, a_src, a_dst);
    k_scan1<<<gS, SCAN_B>>>();
    k_scan3<<<gN, 256>>>(x_a, x_b);
    k_fill<<<gE, 256>>>(ei_a, ei_b);
    k_gat_gather<<<gW, 256>>>(Wgat, bgat);
    k_gcn1<<<gP1, 256>>>(Wgcn, bgcn);
    k_gcn2_mlp<<<gP2, 256>>>(Wgcn + U * U, bgcn + U, ba, bb,
                             W1, b1, W2, b2, W3, b3);
    k_final<<<2, 256>>>((float*)d_out);
}

// round 15
// speedup vs baseline: 1.9025x; 1.0021x over previous
#include <cuda_runtime.h>
#include <cuda_fp16.h>
#include <math.h>

#define N_NODES 50000
#define NSTR    (N_NODES + 1)   // feature-row stride; row N_NODES = reserved zero row
#define N_EDGES 800000
#define E_TOT   850000          // edges + self loops
#define NE4     (N_EDGES / 4)   // 200000
#define NF4     (E_TOT / 4)     // 212500 (incl. self-loop tail)
#define U       64
#define NG      512
#define F_IN    9
#define SCAN_B  1024
#define SCAN_NB ((N_NODES + SCAN_B - 1) / SCAN_B)   // 49
#define NTILES  ((N_NODES + 15) / 16)               // 3125
#define FULL    0xffffffffu

// ---------------- scratch (device globals; zero-initialized at load) --------
__device__ uint2  g_bufA[2 * NSTR * 16];      // fp16 features*dinv; row N_NODES stays 0
__device__ uint2  g_bufB[2 * NSTR * 16];
__device__ float4 g_xpack[2 * N_NODES * 2];   // 32B/node: [as_f32, x0..x8 f16, pad]
__device__ float  g_ad[2 * N_NODES];
__device__ float  g_dinv[2 * N_NODES];
__device__ int    g_deg[2 * N_NODES];         // real-edge count; re-zeroed by k_scan3
__device__ int    g_rowtmp[2 * N_NODES];
__device__ int    g_rowptr[2 * (N_NODES + 1)];
__device__ int    g_cursor[2 * N_NODES];
__device__ int    g_bsum[2 * SCAN_NB];
__device__ int    g_csrc[2 * E_TOT];          // src per CSR slot
__device__ float  g_wa[F_IN], g_wd[F_IN];
__device__ float  g_psum[2 * NG];             // re-zeroed by k_final each pass
__device__ float  g_pcnt[2 * NG];

// fast tanh: ~7 SASS inst; rel err ~1e-6
__device__ __forceinline__ float ftanh(float x) {
    float e = __expf(2.f * x);
    return 1.f - __fdividef(2.f, e + 1.f);
}

// ---------------- CSR build ----------------
// k_deg: 4 real edges/thread (self-loops folded analytically); block0 computes wa/wd
__global__ void k_deg(const int* __restrict__ ei_a, const int* __restrict__ ei_b,
                      const float* __restrict__ W, const float* __restrict__ a_src,
                      const float* __restrict__ a_dst) {
    if (blockIdx.x == 0 && blockIdx.y == 0) {
        int t = threadIdx.x;
        if (t < F_IN) {
            float s = 0.f;
            for (int c = 0; c < U; c++) s += W[t * U + c] * a_src[c];
            g_wa[t] = s;
        } else if (t >= 16 && t < 16 + F_IN) {
            int f = t - 16;
            float s = 0.f;
            for (int c = 0; c < U; c++) s += W[f * U + c] * a_dst[c];
            g_wd[f] = s;
        }
    }
    int br = blockIdx.y;
    int i = blockIdx.x * blockDim.x + threadIdx.x;
    if (i >= NE4) return;
    const int4* dst4 = reinterpret_cast<const int4*>((br ? ei_b : ei_a) + N_EDGES);
    int4 d = dst4[i];
    int* deg = g_deg + br * N_NODES;
    atomicAdd(&deg[d.x], 1);
    atomicAdd(&deg[d.y], 1);
    atomicAdd(&deg[d.z], 1);
    atomicAdd(&deg[d.w], 1);
}
__global__ void k_scan1() {
    __shared__ int sm[SCAN_B];
    int br = blockIdx.y;
    int t = threadIdx.x;
    int i = blockIdx.x * SCAN_B + t;
    int v = (i < N_NODES) ? (g_deg[br * N_NODES + i] + 1) : 0;   // +1 self loop
    sm[t] = v;
    __syncthreads();
#pragma unroll
    for (int off = 1; off < SCAN_B; off <<= 1) {
        int add = (t >= off) ? sm[t - off] : 0;
        __syncthreads();
        sm[t] += add;
        __syncthreads();
    }
    if (i < N_NODES) g_rowtmp[br * N_NODES + i] = sm[t];
    if (t == SCAN_B - 1) g_bsum[br * SCAN_NB + blockIdx.x] = sm[t];
}
// scan3: finalize CSR + dinv + 32B packed [as_f32, x f16]; re-zero deg
__global__ void k_scan3(const float* __restrict__ xa, const float* __restrict__ xb) {
    __shared__ int bsm[SCAN_NB];
    int br = blockIdx.y;
    int t = threadIdx.x;
    if (t < SCAN_NB) bsm[t] = g_bsum[br * SCAN_NB + t];
    __syncthreads();
    int i = blockIdx.x * blockDim.x + t;
    if (i >= N_NODES) return;
    int blk = i / SCAN_B;
    int pre = 0;
    for (int b = 0; b < blk; b++) pre += bsm[b];
    int incl = g_rowtmp[br * N_NODES + i] + pre;
    int d = g_deg[br * N_NODES + i] + 1;       // + self loop
    g_deg[br * N_NODES + i] = 0;               // restore zero for next replay
    g_rowptr[br * (N_NODES + 1) + i + 1] = incl;
    g_cursor[br * N_NODES + i] = incl - d;
    g_dinv[br * N_NODES + i] = rsqrtf((float)d);
    if (i == 0) g_rowptr[br * (N_NODES + 1)] = 0;
    const float* x = br ? xb : xa;
    const float* xi = x + i * F_IN;
    float v[F_IN];
    float as = 0.f, ad = 0.f;
#pragma unroll
    for (int f = 0; f < F_IN; f++) {
        v[f] = xi[f];
        as += v[f] * g_wa[f];
        ad += v[f] * g_wd[f];
    }
    g_ad[br * N_NODES + i] = ad;
    __half2 h01 = __floats2half2_rn(v[0], v[1]);
    __half2 h23 = __floats2half2_rn(v[2], v[3]);
    __half2 h45 = __floats2half2_rn(v[4], v[5]);
    __half2 h67 = __floats2half2_rn(v[6], v[7]);
    __half2 h8z = __floats2half2_rn(v[8], 0.f);
    float4* xp = g_xpack + ((size_t)br * N_NODES + i) * 2;
    float4 q0, q1;
    q0.x = as;
    q0.y = __uint_as_float(*(unsigned*)&h01);
    q0.z = __uint_as_float(*(unsigned*)&h23);
    q0.w = __uint_as_float(*(unsigned*)&h45);
    q1.x = __uint_as_float(*(unsigned*)&h67);
    q1.y = __uint_as_float(*(unsigned*)&h8z);
    q1.z = 0.f; q1.w = 0.f;
    xp[0] = q0;
    xp[1] = q1;
}
// fill: 4 edges/thread; tail range covers self loops
__global__ void k_fill(const int* __restrict__ ei_a, const int* __restrict__ ei_b) {
    int br = blockIdx.y;
    int i = blockIdx.x * blockDim.x + threadIdx.x;
    if (i >= NF4) return;
    int* cur = g_cursor + br * N_NODES;
    int* cs  = g_csrc + br * E_TOT;
    if (i < NE4) {
        const int* ei = br ? ei_b : ei_a;
        int4 s = reinterpret_cast<const int4*>(ei)[i];
        int4 d = reinterpret_cast<const int4*>(ei + N_EDGES)[i];
        int p0 = atomicAdd(&cur[d.x], 1);
        int p1 = atomicAdd(&cur[d.y], 1);
        int p2 = atomicAdd(&cur[d.z], 1);
        int p3 = atomicAdd(&cur[d.w], 1);
        cs[p0] = s.x; cs[p1] = s.y; cs[p2] = s.z; cs[p3] = s.w;
    } else {
        int base = (i - NE4) * 4;
#pragma unroll
        for (int j = 0; j < 4; j++) {
            int n = base + j;
            int p = atomicAdd(&cur[n], 1);
            cs[p] = n;
        }
    }
}

// ---------------- GAT: softmax aggregate of 32B packed x, then @W -----------
__global__ void k_gat_gather(const float* __restrict__ W, const float* __restrict__ b) {
    __shared__ float Ws[F_IN * U];
    __shared__ float bs[U];
    int tid = threadIdx.x;
    for (int i = tid; i < F_IN * U; i += blockDim.x) Ws[i] = W[i];
    if (tid < U) bs[tid] = b[tid];
    __syncthreads();
    int br = blockIdx.y;
    int lane = tid & 31;
    int node = blockIdx.x * (blockDim.x >> 5) + (tid >> 5);
    if (node >= N_NODES) return;
    const int*    cs = g_csrc + br * E_TOT;
    const int*    rp = g_rowptr + br * (N_NODES + 1);
    const float4* xp = g_xpack + (size_t)br * N_NODES * 2;
    int k0 = rp[node], k1 = rp[node + 1];
    float ad_n = g_ad[br * N_NODES + node];
    float acc[F_IN] = {0, 0, 0, 0, 0, 0, 0, 0, 0};
    float ssum = 0.f;
    for (int k = k0 + lane; k < k1; k += 32) {
        int s = cs[k];
        float4 q0 = xp[s * 2];
        float4 q1 = xp[s * 2 + 1];
        float e = q0.x + ad_n;
        e = e > 0.f ? e : 0.2f * e;
        e = fminf(e, 80.f);
        float ex = __expf(e);
        ssum += ex;
        unsigned u01 = __float_as_uint(q0.y), u23 = __float_as_uint(q0.z);
        unsigned u45 = __float_as_uint(q0.w), u67 = __float_as_uint(q1.x);
        unsigned u8z = __float_as_uint(q1.y);
        float2 x01 = __half22float2(*(__half2*)&u01);
        float2 x23 = __half22float2(*(__half2*)&u23);
        float2 x45 = __half22float2(*(__half2*)&u45);
        float2 x67 = __half22float2(*(__half2*)&u67);
        float2 x8z = __half22float2(*(__half2*)&u8z);
        acc[0] += ex * x01.x; acc[1] += ex * x01.y;
        acc[2] += ex * x23.x; acc[3] += ex * x23.y;
        acc[4] += ex * x45.x; acc[5] += ex * x45.y;
        acc[6] += ex * x67.x; acc[7] += ex * x67.y;
        acc[8] += ex * x8z.x;
    }
#pragma unroll
    for (int o = 16; o > 0; o >>= 1) {
        ssum += __shfl_xor_sync(FULL, ssum, o);
#pragma unroll
        for (int f = 0; f < F_IN; f++) acc[f] += __shfl_xor_sync(FULL, acc[f], o);
    }
    float inv = 1.f / ssum;
    int c0 = 2 * lane;
    float y0 = bs[c0], y1 = bs[c0 + 1];
#pragma unroll
    for (int f = 0; f < F_IN; f++) {
        float v = acc[f] * inv;
        y0 += v * Ws[f * U + c0];
        y1 += v * Ws[f * U + c0 + 1];
    }
    float dn = g_dinv[br * N_NODES + node];   // pre-scale for GCN1's gather
    __half2* out2 = reinterpret_cast<__half2*>(g_bufA) + ((size_t)br * NSTR + node) * 32;
    out2[lane] = __floats2half2_rn(ftanh(y0) * dn, ftanh(y1) * dn);
}

// GEMV via smem-broadcast x (16B-aligned stage; offsets 0/68 floats bank-free)
#define STAGE_F 136
__device__ __forceinline__ void gemv64(const float4* __restrict__ Wsm,
                                       float* stage, int half_off, int sub,
                                       float v0, float v1, float v2, float v3,
                                       float& y0, float& y1, float& y2, float& y3) {
    *reinterpret_cast<float4*>(stage + half_off + sub * 4) = make_float4(v0, v1, v2, v3);
    __syncwarp();
    const float* xs = stage + half_off;
#pragma unroll 4
    for (int q = 0; q < 16; q++) {
        float4 xv = *reinterpret_cast<const float4*>(xs + q * 4);
        float4 w0 = Wsm[(4 * q + 0) * 16 + sub];
        float4 w1 = Wsm[(4 * q + 1) * 16 + sub];
        float4 w2 = Wsm[(4 * q + 2) * 16 + sub];
        float4 w3 = Wsm[(4 * q + 3) * 16 + sub];
        y0 += xv.x * w0.x + xv.y * w1.x + xv.z * w2.x + xv.w * w3.x;
        y1 += xv.x * w0.y + xv.y * w1.y + xv.z * w2.y + xv.w * w3.y;
        y2 += xv.x * w0.z + xv.y * w1.z + xv.z * w2.z + xv.w * w3.z;
        y3 += xv.x * w0.w + xv.y * w1.w + xv.z * w2.w + xv.w * w3.w;
    }
    __syncwarp();   // WAR guard before next staging round
}

// gather core: plain sum of pre-scaled features; padding -> zero row N_NODES
__device__ __forceinline__ void gcn_edge_gather(const int* __restrict__ cs,
                                                const int* __restrict__ rp,
                                                const uint2* __restrict__ x4,
                                                int node, bool valid,
                                                int gbase, int sub,
                                                float& a0, float& a1, float& a2, float& a3) {
    int k0 = 0, k1 = 0;
    if (valid) { k0 = rp[node]; k1 = rp[node + 1]; }
    int trips = (k1 - k0 + 15) >> 4;
    trips = max(trips, __shfl_xor_sync(FULL, trips, 16));
    a0 = 0.f; a1 = 0.f; a2 = 0.f; a3 = 0.f;
    for (int t = 0; t < trips; t++) {
        int k = k0 + t * 16 + sub;
        int s_l = (k < k1) ? cs[k] : N_NODES;   // zero row for padding
#pragma unroll
        for (int j = 0; j < 16; j++) {
            int s = __shfl_sync(FULL, s_l, gbase | j);
            uint2 v = x4[s * 16 + sub];
            float2 f0 = __half22float2(*(__half2*)&v.x);
            float2 f1 = __half22float2(*(__half2*)&v.y);
            a0 += f0.x; a1 += f0.y;
            a2 += f1.x; a3 += f1.y;
        }
    }
}

// ---------------- GCN layer 1: persistent, 2 nodes/warp, bufA -> bufB --------
__global__ void __launch_bounds__(256) k_gcn1(const float* __restrict__ W,
                                              const float* __restrict__ b) {
    __shared__ float4 Ws4[U * U / 4];
    __shared__ float4 bs4[U / 4];
    __shared__ __align__(16) float xstage[8][STAGE_F];
    int tid = threadIdx.x;
    for (int i = tid; i < U * U; i += blockDim.x) ((float*)Ws4)[i] = W[i];
    if (tid < U) ((float*)bs4)[tid] = b[tid];
    __syncthreads();
    int br = blockIdx.y;
    int lane = tid & 31, warp = tid >> 5;
    int sub = lane & 15, gbase = lane & 16;
    int half_off = (lane >> 4) * 68;
    float* stage = xstage[warp];
    const int*   cs = g_csrc + br * E_TOT;
    const int*   rp = g_rowptr + br * (N_NODES + 1);
    const float* dinv = g_dinv + br * N_NODES;
    const uint2* x4 = g_bufA + (size_t)br * NSTR * 16;
    uint2* outb = g_bufB + (size_t)br * NSTR * 16;
    for (int tile = blockIdx.x; tile < NTILES; tile += gridDim.x) {
        int node = (tile * 8 + warp) * 2 + (lane >> 4);
        bool valid = node < N_NODES;
        float dn = valid ? dinv[node] : 0.f;
        float a0, a1, a2, a3;
        gcn_edge_gather(cs, rp, x4, node, valid, gbase, sub, a0, a1, a2, a3);
        a0 *= dn; a1 *= dn; a2 *= dn; a3 *= dn;
        float4 bv = bs4[sub];
        float y0 = bv.x, y1 = bv.y, y2 = bv.z, y3 = bv.w;
        gemv64(Ws4, stage, half_off, sub, a0, a1, a2, a3, y0, y1, y2, y3);
        if (valid) {
            __half2 h0 = __floats2half2_rn(ftanh(y0) * dn, ftanh(y1) * dn);
            __half2 h1 = __floats2half2_rn(ftanh(y2) * dn, ftanh(y3) * dn);
            uint2 o;
            o.x = *(unsigned*)&h0; o.y = *(unsigned*)&h1;
            outb[node * 16 + sub] = o;
        }
    }
}

// ---------------- GCN layer 2 + MLP + mean-pool, persistent, 2 nodes/warp ----
__global__ void __launch_bounds__(256) k_gcn2_mlp(
                           const float* __restrict__ W, const float* __restrict__ b,
                           const int* __restrict__ ba, const int* __restrict__ bb,
                           const float* __restrict__ W1, const float* __restrict__ b1,
                           const float* __restrict__ W2, const float* __restrict__ b2,
                           const float* __restrict__ W3, const float* __restrict__ b3) {
    __shared__ float4 Ws4[U * U / 4], W1s4[U * U / 4];
    __shared__ float2 W2s2[U * 16];
    __shared__ float4 bs4[U / 4], b1s4[U / 4];
    __shared__ float  b2s[32], W3s[32], b3s;
    __shared__ __align__(16) float xstage[8][STAGE_F];
    int tid = threadIdx.x;
    for (int i = tid; i < U * U; i += blockDim.x) {
        ((float*)Ws4)[i] = W[i];
        ((float*)W1s4)[i] = W1[i];
    }
    for (int i = tid; i < U * 32; i += blockDim.x) ((float*)W2s2)[i] = W2[i];
    if (tid < U)  { ((float*)bs4)[tid] = b[tid]; ((float*)b1s4)[tid] = b1[tid]; }
    if (tid < 32) { b2s[tid] = b2[tid]; W3s[tid] = W3[tid]; }
    if (tid == 0) b3s = b3[0];
    __syncthreads();
    int br = blockIdx.y;
    int lane = tid & 31, warp = tid >> 5;
    int sub = lane & 15, gbase = lane & 16;
    int half_off = (lane >> 4) * 68;
    float* stage = xstage[warp];
    const int*   cs = g_csrc + br * E_TOT;
    const int*   rp = g_rowptr + br * (N_NODES + 1);
    const float* dinv = g_dinv + br * N_NODES;
    const uint2* x4 = g_bufB + (size_t)br * NSTR * 16;
    const int* batch = br ? bb : ba;
    for (int tile = blockIdx.x; tile < NTILES; tile += gridDim.x) {
        int node = (tile * 8 + warp) * 2 + (lane >> 4);
        bool valid = node < N_NODES;
        float dn = valid ? dinv[node] : 0.f;
        float a0, a1, a2, a3;
        gcn_edge_gather(cs, rp, x4, node, valid, gbase, sub, a0, a1, a2, a3);
        a0 *= dn; a1 *= dn; a2 *= dn; a3 *= dn;
        // GCN GEMV + tanh
        float4 bv = bs4[sub];
        float y0 = bv.x, y1 = bv.y, y2 = bv.z, y3 = bv.w;
        gemv64(Ws4, stage, half_off, sub, a0, a1, a2, a3, y0, y1, y2, y3);
        y0 = ftanh(y0); y1 = ftanh(y1); y2 = ftanh(y2); y3 = ftanh(y3);
        // MLP1 GEMV + tanh
        float4 b1v = b1s4[sub];
        float z0 = b1v.x, z1 = b1v.y, z2 = b1v.z, z3 = b1v.w;
        gemv64(W1s4, stage, half_off, sub, y0, y1, y2, y3, z0, z1, z2, z3);
        z0 = ftanh(z0); z1 = ftanh(z1); z2 = ftanh(z2); z3 = ftanh(z3);
        // MLP2 (64->32): stage z, broadcast-read per q
        *reinterpret_cast<float4*>(stage + half_off + sub * 4) =
            make_float4(z0, z1, z2, z3);
        __syncwarp();
        float p0 = b2s[2 * sub], p1 = b2s[2 * sub + 1];
        const float* zs = stage + half_off;
#pragma unroll 4
        for (int q = 0; q < 16; q++) {
            float4 zv = *reinterpret_cast<const float4*>(zs + q * 4);
            float2 w0 = W2s2[(4 * q + 0) * 16 + sub];
            float2 w1 = W2s2[(4 * q + 1) * 16 + sub];
            float2 w2 = W2s2[(4 * q + 2) * 16 + sub];
            float2 w3 = W2s2[(4 * q + 3) * 16 + sub];
            p0 += zv.x * w0.x + zv.y * w1.x + zv.z * w2.x + zv.w * w3.x;
            p1 += zv.x * w0.y + zv.y * w1.y + zv.z * w2.y + zv.w * w3.y;
        }
        __syncwarp();
        p0 = ftanh(p0); p1 = ftanh(p1);
        // MLP3 (32->1), reduce within 16-lane group
        float c = p0 * W3s[2 * sub] + p1 * W3s[2 * sub + 1];
#pragma unroll
        for (int o = 8; o > 0; o >>= 1) c += __shfl_xor_sync(FULL, c, o);
        if (valid && sub == 0) {
            int g = batch[node];
            atomicAdd(&g_psum[br * NG + g], c + b3s);
            atomicAdd(&g_pcnt[br * NG + g], 1.0f);
        }
    }
}

// ---------------- final: output + restore pool zeros for next replay --------
__global__ void k_final(float* __restrict__ out) {
    int g = blockIdx.x * blockDim.x + threadIdx.x;
    if (g >= NG) return;
    float ua = g_psum[g]      / fmaxf(g_pcnt[g], 1.f);
    float ub = g_psum[NG + g] / fmaxf(g_pcnt[NG + g], 1.f);
    out[g] = 1.f / (1.f + expf(-(ub - ua)));
    g_psum[g] = 0.f; g_psum[NG + g] = 0.f;
    g_pcnt[g] = 0.f; g_pcnt[NG + g] = 0.f;
}

// ---------------- host orchestration ----------------
extern "C" void kernel_launch(void* const* d_in, const int* in_sizes, int n_in,
                              void* d_out, int out_size) {
    const float* x_a   = (const float*)d_in[0];
    const float* x_b   = (const float*)d_in[1];
    const int*   ei_a  = (const int*)  d_in[2];
    const int*   ei_b  = (const int*)  d_in[3];
    const int*   ba    = (const int*)  d_in[4];
    const int*   bb    = (const int*)  d_in[5];
    const float* Wgat  = (const float*)d_in[6];
    const float* a_src = (const float*)d_in[7];
    const float* a_dst = (const float*)d_in[8];
    const float* bgat  = (const float*)d_in[9];
    const float* Wgcn  = (const float*)d_in[10];
    const float* bgcn  = (const float*)d_in[11];
    const float* W1    = (const float*)d_in[12];
    const float* b1    = (const float*)d_in[13];
    const float* W2    = (const float*)d_in[14];
    const float* b2    = (const float*)d_in[15];
    const float* W3    = (const float*)d_in[16];
    const float* b3    = (const float*)d_in[17];

    dim3 gD((NE4 + 255) / 256, 2);       // deg: 4 edges/thread
    dim3 gF((NF4 + 255) / 256, 2);       // fill: 4 edges/thread incl. self loops
    dim3 gS(SCAN_NB, 2);
    dim3 gN((N_NODES + 255) / 256, 2);
    dim3 gW((N_NODES + 7) / 8, 2);       // GAT: 1 node/warp
    dim3 gP1(592, 2);                     // persistent GCN1 (8 blocks/SM)
    dim3 gP2(296, 2);                     // persistent GCN2 (4 blocks/SM by smem)

    k_deg<<<gD, 256>>>(ei_a, ei_b, Wgat, a_src, a_dst);
    k_scan1<<<gS, SCAN_B>>>();
    k_scan3<<<gN, 256>>>(x_a, x_b);
    k_fill<<<gF, 256>>>(ei_a, ei_b);
    k_gat_gather<<<gW, 256>>>(Wgat, bgat);
    k_gcn1<<<gP1, 256>>>(Wgcn, bgcn);
    k_gcn2_mlp<<<gP2, 256>>>(Wgcn + U * U, bgcn + U, ba, bb,
                             W1, b1, W2, b2, W3, b3);
    k_final<<<2, 256>>>((float*)d_out);
}